// round 11
// baseline (speedup 1.0000x reference)
#include <cuda_runtime.h>
#include <cuda_fp16.h>
#include <cstdint>

// Problem constants (B=256 graphs, N=512 nodes/graph, D=128, T=64)
#define NT   131072
#define NTC2 48              // CSR capacity per node (mean in-deg 16, ~8 sigma)
#define DD   128
#define TT   64
#define NPG  512
#define LOG2NPG 9

// ---------------- device scratch (static, no allocation) ----------------
__device__ __align__(16) float  g_Pf[TT * DD];              // emb_table @ W1, fp32
__device__ __align__(16) __half g_ah[(size_t)NT * DD];      // a = invin * sum x, fp16

// ---------------- packed helpers ----------------
__device__ __forceinline__ void fma2(uint64_t& d, uint64_t a, uint64_t b) {
    asm("fma.rn.f32x2 %0, %1, %2, %0;" : "+l"(d) : "l"(a), "l"(b));
}
__device__ __forceinline__ uint64_t dup2(float x) {
    uint64_t r;
    asm("mov.b64 %0, {%1, %1};" : "=l"(r) : "f"(x));
    return r;
}
__device__ __forceinline__ void unpack2(uint64_t v, float& lo, float& hi) {
    asm("mov.b64 {%0, %1}, %2;" : "=f"(lo), "=f"(hi) : "l"(v));
}
__device__ __forceinline__ uint64_t h2f(uint32_t h) {   // half2 -> packed float2
    float2 f = __half22float2(*(__half2*)&h);
    uint64_t r;
    asm("mov.b64 %0, {%1, %2};" : "=l"(r) : "f"(f.x), "f"(f.y));
    return r;
}
__device__ __forceinline__ __half2 u2h(uint32_t v) { return *(__half2*)&v; }

// ---------------- kernels ----------------

__global__ void k_nop() {}

// blocks 0..63: P = emb_table @ W1 -> fp32. blocks 64..127: zero out.
__global__ void k_embinit(const float* __restrict__ emb, const float* __restrict__ W1,
                          float* __restrict__ out, int out_size) {
    int b = blockIdx.x;
    if (b < TT) {
        __shared__ float er[DD];
        int d = threadIdx.x;
        er[d] = emb[b * DD + d];
        __syncthreads();
        float s = 0.0f;
        #pragma unroll 8
        for (int k = 0; k < DD; k++) s = fmaf(er[k], W1[k * DD + d], s);
        g_Pf[b * DD + d] = s;
    } else {
        int idx = (b - TT) * DD + threadIdx.x;
        for (int i = idx; i < out_size; i += TT * DD) out[i] = 0.0f;
    }
}

// Fully fused per-graph kernel, one CTA per graph (1024 threads).
// Stage A: build local CSR (u16, padded to 4 with sentinel 512), smem atomics.
// Stage B: x[v] = wo[v]*relu(inv[v]*sum_u wo[u]*P[type[u]] + b1) -> SMEM fp16
//          (P fp32 in SMEM: 1 LDS.128/edge; (wo,off) packed float2 broadcast)
// Stage C: a[v] = inv[v]*sum_u x[u] (half2 pre-reduction tree)   -> global fp16
#define AGB_CSR  0
#define AGB_X    49152                     // 513 rows x 256B = 131328
#define AGB_P    180480                    // fp32 P: 32768
#define AGB_WOFF 213248                    // float2[513] = 4104 -> 4112
#define AGB_INV  217360                    // 2048
#define AGB_CNT  219408                    // 2048
#define AGB_DEG  221456                    // 2048
#define AGG_SMEM 223504
__global__ void __launch_bounds__(1024, 1) k_agg(const int* __restrict__ feat,
                                                 const float* __restrict__ b1,
                                                 const int4* __restrict__ src4,
                                                 const int4* __restrict__ dst4,
                                                 int epg4) {
    extern __shared__ char sm[];
    unsigned short* s_csr = (unsigned short*)(sm + AGB_CSR);
    uint2*  s_x    = (uint2*)(sm + AGB_X);
    float4* s_P4   = (float4*)(sm + AGB_P);
    float2* s_woff = (float2*)(sm + AGB_WOFF);
    float*  s_inv  = (float*)(sm + AGB_INV);
    int*    s_cnt  = (int*)(sm + AGB_CNT);
    int*    s_deg  = (int*)(sm + AGB_DEG);

    int tid = threadIdx.x, lane = tid & 31, w = tid >> 5;
    int g = blockIdx.x, vbase = g << LOG2NPG;

    if (tid < NPG) { s_cnt[tid] = 0; s_deg[tid] = 0; }
    {   // stage P fp32 (32KB)
        const float4* gP4 = (const float4*)g_Pf;
        s_P4[tid] = gP4[tid];
        s_P4[tid + 1024] = gP4[tid + 1024];
    }
    __syncthreads();

    // ---- stage A: build local CSR from this graph's edge slice ----
    const int4* sp = src4 + (size_t)g * epg4;
    const int4* dp = dst4 + (size_t)g * epg4;
    for (int i = tid; i < epg4; i += 1024) {
        int4 s = sp[i], d = dp[i];
        int sl, dl, p;
        sl = s.x & (NPG - 1); dl = d.x & (NPG - 1);
        atomicAdd(&s_deg[sl], 1);
        p = atomicAdd(&s_cnt[dl], 1);
        if (p < NTC2) s_csr[dl * NTC2 + p] = (unsigned short)sl;
        sl = s.y & (NPG - 1); dl = d.y & (NPG - 1);
        atomicAdd(&s_deg[sl], 1);
        p = atomicAdd(&s_cnt[dl], 1);
        if (p < NTC2) s_csr[dl * NTC2 + p] = (unsigned short)sl;
        sl = s.z & (NPG - 1); dl = d.z & (NPG - 1);
        atomicAdd(&s_deg[sl], 1);
        p = atomicAdd(&s_cnt[dl], 1);
        if (p < NTC2) s_csr[dl * NTC2 + p] = (unsigned short)sl;
        sl = s.w & (NPG - 1); dl = d.w & (NPG - 1);
        atomicAdd(&s_deg[sl], 1);
        p = atomicAdd(&s_cnt[dl], 1);
        if (p < NTC2) s_csr[dl * NTC2 + p] = (unsigned short)sl;
    }
    __syncthreads();

    if (tid < NPG) {
        int draw = s_cnt[tid];
        int dq = s_deg[tid];
        int di = draw > NTC2 ? NTC2 : draw;
        int c4 = (di + 3) & ~3;
        for (int p = di; p < c4; p++) s_csr[tid * NTC2 + p] = (unsigned short)NPG;
        s_cnt[tid] = c4;
        float wo = rsqrtf((float)(dq > 1 ? dq : 1));
        s_woff[tid] = make_float2(wo, __int_as_float(feat[vbase + tid] * 32));
        s_inv[tid]  = rsqrtf((float)(draw > 1 ? draw : 1));
    }
    if (tid == 0) s_woff[NPG] = make_float2(0.f, __int_as_float(0));
    __syncthreads();

    float4 bb = ((const float4*)b1)[lane];

    // ---- stage B: compute x into SMEM (fp16) ----
    #pragma unroll 1
    for (int s = 0; s < 16; s++) {
        int lv = (w << 4) + s;
        int cnt = s_cnt[lv];                    // multiple of 4
        const unsigned short* row = s_csr + lv * NTC2;
        float4 acc = make_float4(0.f, 0.f, 0.f, 0.f);
        for (int base = 0; base < cnt; base += 32) {
            int m = cnt - base; if (m > 32) m = 32;
            int ul = (lane < m) ? row[base + lane] : NPG;
            for (int j = 0; j < m; j += 4) {
                #pragma unroll
                for (int jj = 0; jj < 4; jj++) {
                    int u = __shfl_sync(0xffffffffu, ul, j + jj);
                    float2 wf = s_woff[u];           // broadcast LDS.64
                    float wj = wf.x;
                    int   oj = __float_as_int(wf.y);
                    float4 p = s_P4[oj + lane];      // LDS.128, full fp32 row
                    acc.x = fmaf(wj, p.x, acc.x);
                    acc.y = fmaf(wj, p.y, acc.y);
                    acc.z = fmaf(wj, p.z, acc.z);
                    acc.w = fmaf(wj, p.w, acc.w);
                }
            }
        }
        float wo = s_woff[lv].x, wi = s_inv[lv];
        __half2 p0 = __floats2half2_rn(wo * fmaxf(fmaf(wi, acc.x, bb.x), 0.f),
                                       wo * fmaxf(fmaf(wi, acc.y, bb.y), 0.f));
        __half2 p1 = __floats2half2_rn(wo * fmaxf(fmaf(wi, acc.z, bb.z), 0.f),
                                       wo * fmaxf(fmaf(wi, acc.w, bb.w), 0.f));
        uint2 st;
        st.x = *(uint32_t*)&p0;
        st.y = *(uint32_t*)&p1;
        s_x[lv * 32 + lane] = st;
    }
    if (tid < 32) s_x[NPG * 32 + tid] = make_uint2(0u, 0u);   // sentinel x row
    __syncthreads();

    // ---- stage C: aggregate x (half2 tree), write a (fp16) to global ----
    #pragma unroll 1
    for (int s = 0; s < 16; s++) {
        int lv = (w << 4) + s;
        int cnt = s_cnt[lv];
        const unsigned short* row = s_csr + lv * NTC2;
        float4 acc = make_float4(0.f, 0.f, 0.f, 0.f);
        for (int base = 0; base < cnt; base += 32) {
            int m = cnt - base; if (m > 32) m = 32;
            int ul = (lane < m) ? row[base + lane] : NPG;
            for (int j = 0; j < m; j += 4) {
                int u0 = __shfl_sync(0xffffffffu, ul, j);
                int u1 = __shfl_sync(0xffffffffu, ul, j + 1);
                int u2 = __shfl_sync(0xffffffffu, ul, j + 2);
                int u3 = __shfl_sync(0xffffffffu, ul, j + 3);
                uint2 q0 = s_x[u0 * 32 + lane];
                uint2 q1 = s_x[u1 * 32 + lane];
                uint2 q2 = s_x[u2 * 32 + lane];
                uint2 q3 = s_x[u3 * 32 + lane];
                __half2 sa = __hadd2(__hadd2(u2h(q0.x), u2h(q1.x)),
                                     __hadd2(u2h(q2.x), u2h(q3.x)));
                __half2 sb = __hadd2(__hadd2(u2h(q0.y), u2h(q1.y)),
                                     __hadd2(u2h(q2.y), u2h(q3.y)));
                float2 fa = __half22float2(sa);
                float2 fb = __half22float2(sb);
                acc.x += fa.x; acc.y += fa.y; acc.z += fb.x; acc.w += fb.y;
            }
        }
        float wi = s_inv[lv];
        __half2 q0 = __floats2half2_rn(wi * acc.x, wi * acc.y);
        __half2 q1 = __floats2half2_rn(wi * acc.z, wi * acc.w);
        uint2 st;
        st.x = *(uint32_t*)&q0;
        st.y = *(uint32_t*)&q1;
        ((uint2*)g_ah)[(size_t)(vbase + lv) * 32 + lane] = st;
    }
}

// GEMM (f32x2) + fused epilogue, A fp16 in SMEM — round-9 version (measured 104.9us).
#define GS_W   0
#define GS_A   65536                       // fp16 [16][128] = 4096
#define GS_COL 69632
#define GS_B2  70144
#define GEMM_SMEM 70656
__global__ void __launch_bounds__(256, 2) k_gemm(const float* __restrict__ W2,
                                                 const float* __restrict__ b2,
                                                 float* __restrict__ out) {
    extern __shared__ char smraw[];
    float* Ws    = (float*)(smraw + GS_W);
    unsigned short* Ah = (unsigned short*)(smraw + GS_A);
    float* s_col = (float*)(smraw + GS_COL);
    float* s_b2  = (float*)(smraw + GS_B2);

    int tid = threadIdx.x;
    int row0 = blockIdx.x * 128;

    if (tid < DD) { s_col[tid] = 0.f; s_b2[tid] = b2[tid]; }

    {
        const float4* W24 = (const float4*)W2;
        float4* Ws4 = (float4*)Ws;
        #pragma unroll
        for (int i = tid; i < DD * DD / 4; i += 256) Ws4[i] = W24[i];
    }

    int ty = tid >> 4, tx = tid & 15;
    uint64_t acc[4][8];
    #pragma unroll
    for (int p = 0; p < 4; p++)
        #pragma unroll
        for (int j = 0; j < 8; j++) acc[p][j] = 0ull;

    const uint2* A2 = (const uint2*)g_ah;
    const float4* Ws4c = (const float4*)Ws;

    for (int kb = 0; kb < 8; kb++) {
        __syncthreads();
        #pragma unroll
        for (int l = 0; l < 2; l++) {
            int i = tid + l * 256;
            int r = i >> 2, c4 = i & 3;
            uint2 q = A2[(size_t)(row0 + r) * 32 + kb * 4 + c4];
            Ah[(c4 * 4 + 0) * DD + r] = (unsigned short)(q.x & 0xffffu);
            Ah[(c4 * 4 + 1) * DD + r] = (unsigned short)(q.x >> 16);
            Ah[(c4 * 4 + 2) * DD + r] = (unsigned short)(q.y & 0xffffu);
            Ah[(c4 * 4 + 3) * DD + r] = (unsigned short)(q.y >> 16);
        }
        __syncthreads();
        #pragma unroll
        for (int k = 0; k < 16; k++) {
            uint4 hq = *(const uint4*)(Ah + k * DD + ty * 8);
            uint64_t a0 = h2f(hq.x), a1 = h2f(hq.y), a2 = h2f(hq.z), a3 = h2f(hq.w);
            float4 bA = Ws4c[(kb * 16 + k) * 32 + tx * 2];
            float4 bB = Ws4c[(kb * 16 + k) * 32 + tx * 2 + 1];
            uint64_t bd[8] = {dup2(bA.x), dup2(bA.y), dup2(bA.z), dup2(bA.w),
                              dup2(bB.x), dup2(bB.y), dup2(bB.z), dup2(bB.w)};
            #pragma unroll
            for (int j = 0; j < 8; j++) {
                fma2(acc[0][j], a0, bd[j]);
                fma2(acc[1][j], a1, bd[j]);
                fma2(acc[2][j], a2, bd[j]);
                fma2(acc[3][j], a3, bd[j]);
            }
        }
    }
    __syncthreads();

    #pragma unroll
    for (int j = 0; j < 8; j++) {
        int col = tx * 8 + j;
        float bbv = s_b2[col];
        float s = 0.f;
        #pragma unroll
        for (int p = 0; p < 4; p++) {
            float lo, hi;
            unpack2(acc[p][j], lo, hi);
            s += fmaxf(lo + bbv, 0.f) + fmaxf(hi + bbv, 0.f);
        }
        atomicAdd(&s_col[col], s);
    }
    __syncthreads();
    if (tid < DD)
        atomicAdd(&out[(size_t)(row0 >> LOG2NPG) * DD + tid],
                  s_col[tid] * (1.0f / 512.0f));
}

// ---------------- launch ----------------
extern "C" void kernel_launch(void* const* d_in, const int* in_sizes, int n_in,
                              void* d_out, int out_size) {
    const int*   feat = (const int*)d_in[0];
    const int*   src  = (const int*)d_in[1];
    const int*   dst  = (const int*)d_in[2];
    const float* emb  = (const float*)d_in[3];
    const float* W1   = (const float*)d_in[4];
    const float* b1   = (const float*)d_in[5];
    const float* W2   = (const float*)d_in[6];
    const float* b2   = (const float*)d_in[7];
    float* out = (float*)d_out;

    int n = in_sizes[0];          // 131072
    int E = in_sizes[1];          // 2097152
    int nG = n >> LOG2NPG;        // 256 graphs
    int epg4 = (E / nG) >> 2;     // 2048 int4 per graph

    cudaFuncSetAttribute(k_agg, cudaFuncAttributeMaxDynamicSharedMemorySize, AGG_SMEM);
    cudaFuncSetAttribute(k_gemm, cudaFuncAttributeMaxDynamicSharedMemorySize, GEMM_SMEM);

    // two no-ops keep k_agg in the profiler-captured 4th launch slot
    k_nop<<< 1, 1 >>> ();
    k_nop<<< 1, 1 >>> ();
    k_embinit<<< 128, 128 >>> (emb, W1, out, out_size);
    k_agg   <<< nG, 1024, AGG_SMEM >>> (feat, b1, (const int4*)src, (const int4*)dst, epg4);
    k_gemm  <<< n / 128, 256, GEMM_SMEM >>> (W2, b2, out);
}

// round 12
// speedup vs baseline: 1.1086x; 1.1086x over previous
#include <cuda_runtime.h>
#include <cuda_fp16.h>
#include <cstdint>

// Problem constants (B=256 graphs, N=512 nodes/graph, D=128, T=64)
#define NT   131072
#define NTC2 48              // CSR capacity per node (mean in-deg 16, ~8 sigma)
#define DD   128
#define TT   64
#define NPG  512
#define LOG2NPG 9

// ---------------- device scratch (static, no allocation) ----------------
__device__ __align__(16) __half g_Ph[TT * DD];              // emb_table @ W1, fp16
__device__ __align__(16) __half g_ah[(size_t)NT * DD];      // a = invin * sum x, fp16

// ---------------- packed helpers ----------------
__device__ __forceinline__ void fma2(uint64_t& d, uint64_t a, uint64_t b) {
    asm("fma.rn.f32x2 %0, %1, %2, %0;" : "+l"(d) : "l"(a), "l"(b));
}
__device__ __forceinline__ uint64_t dup2(float x) {
    uint64_t r;
    asm("mov.b64 %0, {%1, %1};" : "=l"(r) : "f"(x));
    return r;
}
__device__ __forceinline__ void unpack2(uint64_t v, float& lo, float& hi) {
    asm("mov.b64 {%0, %1}, %2;" : "=f"(lo), "=f"(hi) : "l"(v));
}
__device__ __forceinline__ uint64_t h2f(uint32_t h) {   // half2 -> packed float2
    float2 f = __half22float2(*(__half2*)&h);
    uint64_t r;
    asm("mov.b64 %0, {%1, %2};" : "=l"(r) : "f"(f.x), "f"(f.y));
    return r;
}
__device__ __forceinline__ __half2 u2h(uint32_t v) { return *(__half2*)&v; }

// ---------------- kernels ----------------

__global__ void k_nop() {}

// blocks 0..63: P = emb_table @ W1 -> fp16. blocks 64..127: zero out.
__global__ void k_embinit(const float* __restrict__ emb, const float* __restrict__ W1,
                          float* __restrict__ out, int out_size) {
    int b = blockIdx.x;
    if (b < TT) {
        __shared__ float er[DD];
        int d = threadIdx.x;
        er[d] = emb[b * DD + d];
        __syncthreads();
        float s = 0.0f;
        #pragma unroll 8
        for (int k = 0; k < DD; k++) s = fmaf(er[k], W1[k * DD + d], s);
        g_Ph[b * DD + d] = __float2half(s);
    } else {
        int idx = (b - TT) * DD + threadIdx.x;
        for (int i = idx; i < out_size; i += TT * DD) out[i] = 0.0f;
    }
}

// Fully fused per-graph kernel, one CTA per graph (1024 threads).
// Stage A: build local CSR (u16, padded to 4 with sentinel 512), smem atomics.
// Stage B: x[v] = wo[v]*relu(inv[v]*sum_u wo[u]*P[type[u]] + b1) -> SMEM fp16
//          (HFMA2 accumulation: 1 shfl + 2 LDS.64 + 2 HFMA2 per edge)
// Stage C: a[v] = inv[v]*sum_u x[u] (half2 pre-reduction tree)   -> global fp16
#define AGB_CSR 0
#define AGB_X   49152                      // 513 rows x 256B = 131328
#define AGB_P   180480                     // fp16 P: 16384
#define AGB_WP  196864                     // uint2[513] = 4104 -> 4112
#define AGB_INV 200976                     // 2048
#define AGB_CNT 203024                     // 2048
#define AGB_DEG 205072                     // 2048
#define AGG_SMEM 207120
__global__ void __launch_bounds__(1024, 1) k_agg(const int* __restrict__ feat,
                                                 const float* __restrict__ b1,
                                                 const int4* __restrict__ src4,
                                                 const int4* __restrict__ dst4,
                                                 int epg4) {
    extern __shared__ char sm[];
    unsigned short* s_csr = (unsigned short*)(sm + AGB_CSR);
    uint2* s_x   = (uint2*)(sm + AGB_X);
    uint2* s_P   = (uint2*)(sm + AGB_P);
    uint2* s_wp  = (uint2*)(sm + AGB_WP);    // {wo as half2, P row offset (uint2 units)}
    float* s_inv = (float*)(sm + AGB_INV);
    int*   s_cnt = (int*)(sm + AGB_CNT);
    int*   s_deg = (int*)(sm + AGB_DEG);

    int tid = threadIdx.x, lane = tid & 31, w = tid >> 5;
    int g = blockIdx.x, vbase = g << LOG2NPG;

    if (tid < NPG) { s_cnt[tid] = 0; s_deg[tid] = 0; }
    {   // stage P fp16 (16KB)
        const uint2* gP2 = (const uint2*)g_Ph;
        s_P[tid] = gP2[tid];
        s_P[tid + 1024] = gP2[tid + 1024];
    }
    __syncthreads();

    // ---- stage A: build local CSR from this graph's edge slice ----
    const int4* sp = src4 + (size_t)g * epg4;
    const int4* dp = dst4 + (size_t)g * epg4;
    for (int i = tid; i < epg4; i += 1024) {
        int4 s = sp[i], d = dp[i];
        int sl, dl, p;
        sl = s.x & (NPG - 1); dl = d.x & (NPG - 1);
        atomicAdd(&s_deg[sl], 1);
        p = atomicAdd(&s_cnt[dl], 1);
        if (p < NTC2) s_csr[dl * NTC2 + p] = (unsigned short)sl;
        sl = s.y & (NPG - 1); dl = d.y & (NPG - 1);
        atomicAdd(&s_deg[sl], 1);
        p = atomicAdd(&s_cnt[dl], 1);
        if (p < NTC2) s_csr[dl * NTC2 + p] = (unsigned short)sl;
        sl = s.z & (NPG - 1); dl = d.z & (NPG - 1);
        atomicAdd(&s_deg[sl], 1);
        p = atomicAdd(&s_cnt[dl], 1);
        if (p < NTC2) s_csr[dl * NTC2 + p] = (unsigned short)sl;
        sl = s.w & (NPG - 1); dl = d.w & (NPG - 1);
        atomicAdd(&s_deg[sl], 1);
        p = atomicAdd(&s_cnt[dl], 1);
        if (p < NTC2) s_csr[dl * NTC2 + p] = (unsigned short)sl;
    }
    __syncthreads();

    if (tid < NPG) {
        int draw = s_cnt[tid];
        int dq = s_deg[tid];
        int di = draw > NTC2 ? NTC2 : draw;
        int c4 = (di + 3) & ~3;
        for (int p = di; p < c4; p++) s_csr[tid * NTC2 + p] = (unsigned short)NPG;
        s_cnt[tid] = c4;
        float wo = rsqrtf((float)(dq > 1 ? dq : 1));
        __half2 woh = __float2half2_rn(wo);
        s_wp[tid] = make_uint2(*(uint32_t*)&woh, (uint32_t)(feat[vbase + tid] * 32));
        s_inv[tid] = rsqrtf((float)(draw > 1 ? draw : 1));
    }
    if (tid == 0) s_wp[NPG] = make_uint2(0u, 0u);
    __syncthreads();

    float4 bb = ((const float4*)b1)[lane];

    // ---- stage B: compute x into SMEM (fp16, HFMA2 accumulation) ----
    #pragma unroll 1
    for (int s = 0; s < 16; s++) {
        int lv = (w << 4) + s;
        int cnt = s_cnt[lv];                    // multiple of 4
        const unsigned short* row = s_csr + lv * NTC2;
        __half2 acc0 = __float2half2_rn(0.f);
        __half2 acc1 = __float2half2_rn(0.f);
        for (int base = 0; base < cnt; base += 32) {
            int m = cnt - base; if (m > 32) m = 32;
            int ul = (lane < m) ? row[base + lane] : NPG;
            for (int j = 0; j < m; j += 4) {
                #pragma unroll
                for (int jj = 0; jj < 4; jj++) {
                    int u = __shfl_sync(0xffffffffu, ul, j + jj);
                    uint2 wp = s_wp[u];              // broadcast LDS.64
                    __half2 woh = u2h(wp.x);
                    uint2 q = s_P[wp.y + lane];      // LDS.64 fp16 row
                    acc0 = __hfma2(u2h(q.x), woh, acc0);
                    acc1 = __hfma2(u2h(q.y), woh, acc1);
                }
            }
        }
        int dq = s_deg[lv];
        float wo = rsqrtf((float)(dq > 1 ? dq : 1));
        float wi = s_inv[lv];
        float2 a01 = __half22float2(acc0);
        float2 a23 = __half22float2(acc1);
        __half2 p0 = __floats2half2_rn(wo * fmaxf(fmaf(wi, a01.x, bb.x), 0.f),
                                       wo * fmaxf(fmaf(wi, a01.y, bb.y), 0.f));
        __half2 p1 = __floats2half2_rn(wo * fmaxf(fmaf(wi, a23.x, bb.z), 0.f),
                                       wo * fmaxf(fmaf(wi, a23.y, bb.w), 0.f));
        uint2 st;
        st.x = *(uint32_t*)&p0;
        st.y = *(uint32_t*)&p1;
        s_x[lv * 32 + lane] = st;
    }
    if (tid < 32) s_x[NPG * 32 + tid] = make_uint2(0u, 0u);   // sentinel x row
    __syncthreads();

    // ---- stage C: aggregate x (half2 tree), write a (fp16) to global ----
    #pragma unroll 1
    for (int s = 0; s < 16; s++) {
        int lv = (w << 4) + s;
        int cnt = s_cnt[lv];
        const unsigned short* row = s_csr + lv * NTC2;
        float4 acc = make_float4(0.f, 0.f, 0.f, 0.f);
        for (int base = 0; base < cnt; base += 32) {
            int m = cnt - base; if (m > 32) m = 32;
            int ul = (lane < m) ? row[base + lane] : NPG;
            for (int j = 0; j < m; j += 4) {
                int u0 = __shfl_sync(0xffffffffu, ul, j);
                int u1 = __shfl_sync(0xffffffffu, ul, j + 1);
                int u2 = __shfl_sync(0xffffffffu, ul, j + 2);
                int u3 = __shfl_sync(0xffffffffu, ul, j + 3);
                uint2 q0 = s_x[u0 * 32 + lane];
                uint2 q1 = s_x[u1 * 32 + lane];
                uint2 q2 = s_x[u2 * 32 + lane];
                uint2 q3 = s_x[u3 * 32 + lane];
                __half2 sa = __hadd2(__hadd2(u2h(q0.x), u2h(q1.x)),
                                     __hadd2(u2h(q2.x), u2h(q3.x)));
                __half2 sb = __hadd2(__hadd2(u2h(q0.y), u2h(q1.y)),
                                     __hadd2(u2h(q2.y), u2h(q3.y)));
                float2 fa = __half22float2(sa);
                float2 fb = __half22float2(sb);
                acc.x += fa.x; acc.y += fa.y; acc.z += fb.x; acc.w += fb.y;
            }
        }
        float wi = s_inv[lv];
        __half2 q0 = __floats2half2_rn(wi * acc.x, wi * acc.y);
        __half2 q1 = __floats2half2_rn(wi * acc.z, wi * acc.w);
        uint2 st;
        st.x = *(uint32_t*)&q0;
        st.y = *(uint32_t*)&q1;
        ((uint2*)g_ah)[(size_t)(vbase + lv) * 32 + lane] = st;
    }
}

// GEMM (f32x2) + fused epilogue, A fp16 in SMEM — round-9 version (measured 104.9us).
#define GS_W   0
#define GS_A   65536                       // fp16 [16][128] = 4096
#define GS_COL 69632
#define GS_B2  70144
#define GEMM_SMEM 70656
__global__ void __launch_bounds__(256, 2) k_gemm(const float* __restrict__ W2,
                                                 const float* __restrict__ b2,
                                                 float* __restrict__ out) {
    extern __shared__ char smraw[];
    float* Ws    = (float*)(smraw + GS_W);
    unsigned short* Ah = (unsigned short*)(smraw + GS_A);
    float* s_col = (float*)(smraw + GS_COL);
    float* s_b2  = (float*)(smraw + GS_B2);

    int tid = threadIdx.x;
    int row0 = blockIdx.x * 128;

    if (tid < DD) { s_col[tid] = 0.f; s_b2[tid] = b2[tid]; }

    {
        const float4* W24 = (const float4*)W2;
        float4* Ws4 = (float4*)Ws;
        #pragma unroll
        for (int i = tid; i < DD * DD / 4; i += 256) Ws4[i] = W24[i];
    }

    int ty = tid >> 4, tx = tid & 15;
    uint64_t acc[4][8];
    #pragma unroll
    for (int p = 0; p < 4; p++)
        #pragma unroll
        for (int j = 0; j < 8; j++) acc[p][j] = 0ull;

    const uint2* A2 = (const uint2*)g_ah;
    const float4* Ws4c = (const float4*)Ws;

    for (int kb = 0; kb < 8; kb++) {
        __syncthreads();
        #pragma unroll
        for (int l = 0; l < 2; l++) {
            int i = tid + l * 256;
            int r = i >> 2, c4 = i & 3;
            uint2 q = A2[(size_t)(row0 + r) * 32 + kb * 4 + c4];
            Ah[(c4 * 4 + 0) * DD + r] = (unsigned short)(q.x & 0xffffu);
            Ah[(c4 * 4 + 1) * DD + r] = (unsigned short)(q.x >> 16);
            Ah[(c4 * 4 + 2) * DD + r] = (unsigned short)(q.y & 0xffffu);
            Ah[(c4 * 4 + 3) * DD + r] = (unsigned short)(q.y >> 16);
        }
        __syncthreads();
        #pragma unroll
        for (int k = 0; k < 16; k++) {
            uint4 hq = *(const uint4*)(Ah + k * DD + ty * 8);
            uint64_t a0 = h2f(hq.x), a1 = h2f(hq.y), a2 = h2f(hq.z), a3 = h2f(hq.w);
            float4 bA = Ws4c[(kb * 16 + k) * 32 + tx * 2];
            float4 bB = Ws4c[(kb * 16 + k) * 32 + tx * 2 + 1];
            uint64_t bd[8] = {dup2(bA.x), dup2(bA.y), dup2(bA.z), dup2(bA.w),
                              dup2(bB.x), dup2(bB.y), dup2(bB.z), dup2(bB.w)};
            #pragma unroll
            for (int j = 0; j < 8; j++) {
                fma2(acc[0][j], a0, bd[j]);
                fma2(acc[1][j], a1, bd[j]);
                fma2(acc[2][j], a2, bd[j]);
                fma2(acc[3][j], a3, bd[j]);
            }
        }
    }
    __syncthreads();

    #pragma unroll
    for (int j = 0; j < 8; j++) {
        int col = tx * 8 + j;
        float bbv = s_b2[col];
        float s = 0.f;
        #pragma unroll
        for (int p = 0; p < 4; p++) {
            float lo, hi;
            unpack2(acc[p][j], lo, hi);
            s += fmaxf(lo + bbv, 0.f) + fmaxf(hi + bbv, 0.f);
        }
        atomicAdd(&s_col[col], s);
    }
    __syncthreads();
    if (tid < DD)
        atomicAdd(&out[(size_t)(row0 >> LOG2NPG) * DD + tid],
                  s_col[tid] * (1.0f / 512.0f));
}

// ---------------- launch ----------------
extern "C" void kernel_launch(void* const* d_in, const int* in_sizes, int n_in,
                              void* d_out, int out_size) {
    const int*   feat = (const int*)d_in[0];
    const int*   src  = (const int*)d_in[1];
    const int*   dst  = (const int*)d_in[2];
    const float* emb  = (const float*)d_in[3];
    const float* W1   = (const float*)d_in[4];
    const float* b1   = (const float*)d_in[5];
    const float* W2   = (const float*)d_in[6];
    const float* b2   = (const float*)d_in[7];
    float* out = (float*)d_out;

    int n = in_sizes[0];          // 131072
    int E = in_sizes[1];          // 2097152
    int nG = n >> LOG2NPG;        // 256 graphs
    int epg4 = (E / nG) >> 2;     // 2048 int4 per graph

    cudaFuncSetAttribute(k_agg, cudaFuncAttributeMaxDynamicSharedMemorySize, AGG_SMEM);
    cudaFuncSetAttribute(k_gemm, cudaFuncAttributeMaxDynamicSharedMemorySize, GEMM_SMEM);

    // two no-ops keep k_agg in the profiler-captured 4th launch slot
    k_nop<<< 1, 1 >>> ();
    k_nop<<< 1, 1 >>> ();
    k_embinit<<< 128, 128 >>> (emb, W1, out, out_size);
    k_agg   <<< nG, 1024, AGG_SMEM >>> (feat, b1, (const int4*)src, (const int4*)dst, epg4);
    k_gemm  <<< n / 128, 256, GEMM_SMEM >>> (W2, b2, out);
}

// round 13
// speedup vs baseline: 1.8276x; 1.6486x over previous
#include <cuda_runtime.h>
#include <cuda_fp16.h>
#include <cstdint>

// Problem constants (B=256 graphs, N=512 nodes/graph, D=128, T=64)
#define NT   131072
#define NTC2 48              // CSR capacity per node (mean in-deg 16, ~8 sigma)
#define DD   128
#define TT   64
#define NPG  512
#define LOG2NPG 9

// ---------------- device scratch (static, no allocation) ----------------
__device__ __align__(16) __half g_Ph[TT * DD];              // emb_table @ W1, fp16
__device__ __align__(16) __half g_ah[(size_t)NT * DD];      // a = invin * sum x, fp16
__device__ __align__(16) uint2  g_Bfh[4096];                // W2 hi, mma-fragment order
__device__ __align__(16) uint2  g_Bfl[4096];                // W2 lo residual, same order

// ---------------- helpers ----------------
__device__ __forceinline__ uint32_t s2u(const void* p) {
    uint32_t a;
    asm("{ .reg .u64 t; cvta.to.shared.u64 t, %1; cvt.u32.u64 %0, t; }" : "=r"(a) : "l"(p));
    return a;
}
__device__ __forceinline__ __half2 u2h(uint32_t v) { return *(__half2*)&v; }

__device__ __forceinline__ void ldsm_x4(uint32_t& r0, uint32_t& r1, uint32_t& r2,
                                        uint32_t& r3, uint32_t saddr) {
    asm volatile("ldmatrix.sync.aligned.m8n8.x4.shared.b16 {%0,%1,%2,%3}, [%4];"
                 : "=r"(r0), "=r"(r1), "=r"(r2), "=r"(r3) : "r"(saddr));
}
// mma m16n8k16 row.col f16xf16 + f32
__device__ __forceinline__ void mma16(float c[4], uint32_t a0, uint32_t a1,
                                      uint32_t a2, uint32_t a3,
                                      uint32_t b0, uint32_t b1) {
    asm volatile(
        "mma.sync.aligned.m16n8k16.row.col.f32.f16.f16.f32 "
        "{%0,%1,%2,%3},{%4,%5,%6,%7},{%8,%9},{%0,%1,%2,%3};"
        : "+f"(c[0]), "+f"(c[1]), "+f"(c[2]), "+f"(c[3])
        : "r"(a0), "r"(a1), "r"(a2), "r"(a3), "r"(b0), "r"(b1));
}

// ---------------- kernels ----------------

// blocks 0..63: P = emb_table @ W1 -> fp16. blocks 64..127: zero out.
__global__ void k_embinit(const float* __restrict__ emb, const float* __restrict__ W1,
                          float* __restrict__ out, int out_size) {
    int b = blockIdx.x;
    if (b < TT) {
        __shared__ float er[DD];
        int d = threadIdx.x;
        er[d] = emb[b * DD + d];
        __syncthreads();
        float s = 0.0f;
        #pragma unroll 8
        for (int k = 0; k < DD; k++) s = fmaf(er[k], W1[k * DD + d], s);
        g_Ph[b * DD + d] = __float2half(s);
    } else {
        int idx = (b - TT) * DD + threadIdx.x;
        for (int i = idx; i < out_size; i += TT * DD) out[i] = 0.0f;
    }
}

// Pack W2 into per-lane mma B-fragment order, hi/lo fp16 split.
// entry i = (ks, nt, lane): n = nt*8 + lane/4, k0 = ks*16 + 2*(lane%4)
// b0 = {B[k0][n], B[k0+1][n]}, b1 = {B[k0+8][n], B[k0+9][n]}
__global__ void k_prepB(const float* __restrict__ W2) {
    int i = blockIdx.x * blockDim.x + threadIdx.x;   // 4096
    int lane = i & 31, nt = (i >> 5) & 15, ks = i >> 9;
    int n = nt * 8 + (lane >> 2);
    int k0 = ks * 16 + 2 * (lane & 3);
    float w00 = W2[k0 * DD + n],       w01 = W2[(k0 + 1) * DD + n];
    float w10 = W2[(k0 + 8) * DD + n], w11 = W2[(k0 + 9) * DD + n];
    __half h00 = __float2half_rn(w00), h01 = __float2half_rn(w01);
    __half h10 = __float2half_rn(w10), h11 = __float2half_rn(w11);
    __half l00 = __float2half_rn(w00 - __half2float(h00));
    __half l01 = __float2half_rn(w01 - __half2float(h01));
    __half l10 = __float2half_rn(w10 - __half2float(h10));
    __half l11 = __float2half_rn(w11 - __half2float(h11));
    __half2 bh0 = __halves2half2(h00, h01), bh1 = __halves2half2(h10, h11);
    __half2 bl0 = __halves2half2(l00, l01), bl1 = __halves2half2(l10, l11);
    g_Bfh[i] = make_uint2(*(uint32_t*)&bh0, *(uint32_t*)&bh1);
    g_Bfl[i] = make_uint2(*(uint32_t*)&bl0, *(uint32_t*)&bl1);
}

// Fully fused per-graph kernel (unchanged from round 12, measured 83.5us).
#define AGB_CSR 0
#define AGB_X   49152
#define AGB_P   180480
#define AGB_WP  196864
#define AGB_INV 200976
#define AGB_CNT 203024
#define AGB_DEG 205072
#define AGG_SMEM 207120
__global__ void __launch_bounds__(1024, 1) k_agg(const int* __restrict__ feat,
                                                 const float* __restrict__ b1,
                                                 const int4* __restrict__ src4,
                                                 const int4* __restrict__ dst4,
                                                 int epg4) {
    extern __shared__ char sm[];
    unsigned short* s_csr = (unsigned short*)(sm + AGB_CSR);
    uint2* s_x   = (uint2*)(sm + AGB_X);
    uint2* s_P   = (uint2*)(sm + AGB_P);
    uint2* s_wp  = (uint2*)(sm + AGB_WP);
    float* s_inv = (float*)(sm + AGB_INV);
    int*   s_cnt = (int*)(sm + AGB_CNT);
    int*   s_deg = (int*)(sm + AGB_DEG);

    int tid = threadIdx.x, lane = tid & 31, w = tid >> 5;
    int g = blockIdx.x, vbase = g << LOG2NPG;

    if (tid < NPG) { s_cnt[tid] = 0; s_deg[tid] = 0; }
    {
        const uint2* gP2 = (const uint2*)g_Ph;
        s_P[tid] = gP2[tid];
        s_P[tid + 1024] = gP2[tid + 1024];
    }
    __syncthreads();

    const int4* sp = src4 + (size_t)g * epg4;
    const int4* dp = dst4 + (size_t)g * epg4;
    for (int i = tid; i < epg4; i += 1024) {
        int4 s = sp[i], d = dp[i];
        int sl, dl, p;
        sl = s.x & (NPG - 1); dl = d.x & (NPG - 1);
        atomicAdd(&s_deg[sl], 1);
        p = atomicAdd(&s_cnt[dl], 1);
        if (p < NTC2) s_csr[dl * NTC2 + p] = (unsigned short)sl;
        sl = s.y & (NPG - 1); dl = d.y & (NPG - 1);
        atomicAdd(&s_deg[sl], 1);
        p = atomicAdd(&s_cnt[dl], 1);
        if (p < NTC2) s_csr[dl * NTC2 + p] = (unsigned short)sl;
        sl = s.z & (NPG - 1); dl = d.z & (NPG - 1);
        atomicAdd(&s_deg[sl], 1);
        p = atomicAdd(&s_cnt[dl], 1);
        if (p < NTC2) s_csr[dl * NTC2 + p] = (unsigned short)sl;
        sl = s.w & (NPG - 1); dl = d.w & (NPG - 1);
        atomicAdd(&s_deg[sl], 1);
        p = atomicAdd(&s_cnt[dl], 1);
        if (p < NTC2) s_csr[dl * NTC2 + p] = (unsigned short)sl;
    }
    __syncthreads();

    if (tid < NPG) {
        int draw = s_cnt[tid];
        int dq = s_deg[tid];
        int di = draw > NTC2 ? NTC2 : draw;
        int c4 = (di + 3) & ~3;
        for (int p = di; p < c4; p++) s_csr[tid * NTC2 + p] = (unsigned short)NPG;
        s_cnt[tid] = c4;
        float wo = rsqrtf((float)(dq > 1 ? dq : 1));
        __half2 woh = __float2half2_rn(wo);
        s_wp[tid] = make_uint2(*(uint32_t*)&woh, (uint32_t)(feat[vbase + tid] * 32));
        s_inv[tid] = rsqrtf((float)(draw > 1 ? draw : 1));
    }
    if (tid == 0) s_wp[NPG] = make_uint2(0u, 0u);
    __syncthreads();

    float4 bb = ((const float4*)b1)[lane];

    #pragma unroll 1
    for (int s = 0; s < 16; s++) {
        int lv = (w << 4) + s;
        int cnt = s_cnt[lv];
        const unsigned short* row = s_csr + lv * NTC2;
        __half2 acc0 = __float2half2_rn(0.f);
        __half2 acc1 = __float2half2_rn(0.f);
        for (int base = 0; base < cnt; base += 32) {
            int m = cnt - base; if (m > 32) m = 32;
            int ul = (lane < m) ? row[base + lane] : NPG;
            for (int j = 0; j < m; j += 4) {
                #pragma unroll
                for (int jj = 0; jj < 4; jj++) {
                    int u = __shfl_sync(0xffffffffu, ul, j + jj);
                    uint2 wp = s_wp[u];
                    __half2 woh = u2h(wp.x);
                    uint2 q = s_P[wp.y + lane];
                    acc0 = __hfma2(u2h(q.x), woh, acc0);
                    acc1 = __hfma2(u2h(q.y), woh, acc1);
                }
            }
        }
        int dq = s_deg[lv];
        float wo = rsqrtf((float)(dq > 1 ? dq : 1));
        float wi = s_inv[lv];
        float2 a01 = __half22float2(acc0);
        float2 a23 = __half22float2(acc1);
        __half2 p0 = __floats2half2_rn(wo * fmaxf(fmaf(wi, a01.x, bb.x), 0.f),
                                       wo * fmaxf(fmaf(wi, a01.y, bb.y), 0.f));
        __half2 p1 = __floats2half2_rn(wo * fmaxf(fmaf(wi, a23.x, bb.z), 0.f),
                                       wo * fmaxf(fmaf(wi, a23.y, bb.w), 0.f));
        uint2 st;
        st.x = *(uint32_t*)&p0;
        st.y = *(uint32_t*)&p1;
        s_x[lv * 32 + lane] = st;
    }
    if (tid < 32) s_x[NPG * 32 + tid] = make_uint2(0u, 0u);
    __syncthreads();

    #pragma unroll 1
    for (int s = 0; s < 16; s++) {
        int lv = (w << 4) + s;
        int cnt = s_cnt[lv];
        const unsigned short* row = s_csr + lv * NTC2;
        float4 acc = make_float4(0.f, 0.f, 0.f, 0.f);
        for (int base = 0; base < cnt; base += 32) {
            int m = cnt - base; if (m > 32) m = 32;
            int ul = (lane < m) ? row[base + lane] : NPG;
            for (int j = 0; j < m; j += 4) {
                int u0 = __shfl_sync(0xffffffffu, ul, j);
                int u1 = __shfl_sync(0xffffffffu, ul, j + 1);
                int u2 = __shfl_sync(0xffffffffu, ul, j + 2);
                int u3 = __shfl_sync(0xffffffffu, ul, j + 3);
                uint2 q0 = s_x[u0 * 32 + lane];
                uint2 q1 = s_x[u1 * 32 + lane];
                uint2 q2 = s_x[u2 * 32 + lane];
                uint2 q3 = s_x[u3 * 32 + lane];
                __half2 sa = __hadd2(__hadd2(u2h(q0.x), u2h(q1.x)),
                                     __hadd2(u2h(q2.x), u2h(q3.x)));
                __half2 sb = __hadd2(__hadd2(u2h(q0.y), u2h(q1.y)),
                                     __hadd2(u2h(q2.y), u2h(q3.y)));
                float2 fa = __half22float2(sa);
                float2 fb = __half22float2(sb);
                acc.x += fa.x; acc.y += fa.y; acc.z += fb.x; acc.w += fb.y;
            }
        }
        float wi = s_inv[lv];
        __half2 q0 = __floats2half2_rn(wi * acc.x, wi * acc.y);
        __half2 q1 = __floats2half2_rn(wi * acc.z, wi * acc.w);
        uint2 st;
        st.x = *(uint32_t*)&q0;
        st.y = *(uint32_t*)&q1;
        ((uint2*)g_ah)[(size_t)(vbase + lv) * 32 + lane] = st;
    }
}

// Tensor-core GEMM (mma.sync m16n8k16 fp16, B hi+lo split) + fused epilogue.
// CTA: 128 rows x 128 cols. Warp w owns cols 16w..16w+15 (ntiles 2w, 2w+1),
// iterates 8 mtiles of 16 rows. A via ldmatrix from padded SMEM (272B rows).
// Epilogue: relu(D + b2) column sums (exact, row-permutation invariant),
// direct store to s_col (disjoint cols per warp), then atomicAdd to out.
#define GS_A   0                            // 128 x 272B = 34816
#define GS_BH  34816                        // 32768
#define GS_BL  67584                        // 32768
#define GS_COL 100352                       // 512
#define GS_B2  100864                       // 512
#define GEMM_SMEM 101376
__global__ void __launch_bounds__(256, 2) k_gemm(const float* __restrict__ b2,
                                                 float* __restrict__ out) {
    extern __shared__ char smraw[];
    uint2* smA2  = (uint2*)(smraw + GS_A);      // padded A tile, stride 34 uint2
    uint2* sBfh  = (uint2*)(smraw + GS_BH);
    uint2* sBfl  = (uint2*)(smraw + GS_BL);
    float* s_col = (float*)(smraw + GS_COL);
    float* s_b2  = (float*)(smraw + GS_B2);

    int tid = threadIdx.x, lane = tid & 31, w = tid >> 5;
    int row0 = blockIdx.x * 128;

    if (tid < DD) s_b2[tid] = b2[tid];

    // stage A tile: 128 rows x 32 uint2, padded to stride 34 uint2 (272B)
    {
        const uint2* A2 = (const uint2*)g_ah + (size_t)row0 * 32;
        #pragma unroll
        for (int l = 0; l < 16; l++) {
            int i = tid + l * 256;
            int r = i >> 5, c = i & 31;
            smA2[r * 34 + c] = A2[r * 32 + c];
        }
    }
    // stage B fragments (hi + lo), coalesced
    #pragma unroll
    for (int l = 0; l < 16; l++) {
        int i = tid + l * 256;
        sBfh[i] = g_Bfh[i];
        sBfl[i] = g_Bfl[i];
    }
    __syncthreads();

    float c[2][8][4];
    #pragma unroll
    for (int j = 0; j < 2; j++)
        #pragma unroll
        for (int mt = 0; mt < 8; mt++)
            #pragma unroll
            for (int q = 0; q < 4; q++) c[j][mt][q] = 0.f;

    // ldmatrix row address: lane l -> row (l&15), k-halfword block (l>>4)
    uint32_t aBase = s2u(smraw) + (uint32_t)(lane & 15) * 272 + ((lane >> 4) << 4);
    int nt0 = 2 * w;

    #pragma unroll
    for (int ks = 0; ks < 8; ks++) {
        uint2 fh0 = sBfh[(ks * 16 + nt0) * 32 + lane];
        uint2 fh1 = sBfh[(ks * 16 + nt0 + 1) * 32 + lane];
        uint2 fl0 = sBfl[(ks * 16 + nt0) * 32 + lane];
        uint2 fl1 = sBfl[(ks * 16 + nt0 + 1) * 32 + lane];
        #pragma unroll
        for (int mt = 0; mt < 8; mt++) {
            uint32_t a0, a1, a2, a3;
            ldsm_x4(a0, a1, a2, a3, aBase + (uint32_t)(mt * 16 * 272 + ks * 32));
            mma16(c[0][mt], a0, a1, a2, a3, fh0.x, fh0.y);
            mma16(c[0][mt], a0, a1, a2, a3, fl0.x, fl0.y);
            mma16(c[1][mt], a0, a1, a2, a3, fh1.x, fh1.y);
            mma16(c[1][mt], a0, a1, a2, a3, fl1.x, fl1.y);
        }
    }

    // epilogue: relu + column sums. cols for (j): (nt0+j)*8 + 2t, +1
    int t = lane & 3;
    #pragma unroll
    for (int j = 0; j < 2; j++) {
        int colb = (nt0 + j) * 8 + 2 * t;
        float b20 = s_b2[colb], b21 = s_b2[colb + 1];
        float s0 = 0.f, s1 = 0.f;
        #pragma unroll
        for (int mt = 0; mt < 8; mt++) {
            s0 += fmaxf(c[j][mt][0] + b20, 0.f) + fmaxf(c[j][mt][2] + b20, 0.f);
            s1 += fmaxf(c[j][mt][1] + b21, 0.f) + fmaxf(c[j][mt][3] + b21, 0.f);
        }
        // reduce over the 8 lanes sharing t (lane bits 2,3,4)
        s0 += __shfl_xor_sync(0xffffffffu, s0, 4);
        s1 += __shfl_xor_sync(0xffffffffu, s1, 4);
        s0 += __shfl_xor_sync(0xffffffffu, s0, 8);
        s1 += __shfl_xor_sync(0xffffffffu, s1, 8);
        s0 += __shfl_xor_sync(0xffffffffu, s0, 16);
        s1 += __shfl_xor_sync(0xffffffffu, s1, 16);
        if (lane < 4) {                     // one lane per t
            s_col[colb] = s0;
            s_col[colb + 1] = s1;
        }
    }
    __syncthreads();
    if (tid < DD)
        atomicAdd(&out[(size_t)(row0 >> LOG2NPG) * DD + tid],
                  s_col[tid] * (1.0f / 512.0f));
}

// ---------------- launch ----------------
extern "C" void kernel_launch(void* const* d_in, const int* in_sizes, int n_in,
                              void* d_out, int out_size) {
    const int*   feat = (const int*)d_in[0];
    const int*   src  = (const int*)d_in[1];
    const int*   dst  = (const int*)d_in[2];
    const float* emb  = (const float*)d_in[3];
    const float* W1   = (const float*)d_in[4];
    const float* b1   = (const float*)d_in[5];
    const float* W2   = (const float*)d_in[6];
    const float* b2   = (const float*)d_in[7];
    float* out = (float*)d_out;

    int n = in_sizes[0];          // 131072
    int E = in_sizes[1];          // 2097152
    int nG = n >> LOG2NPG;        // 256 graphs
    int epg4 = (E / nG) >> 2;     // 2048 int4 per graph

    cudaFuncSetAttribute(k_agg, cudaFuncAttributeMaxDynamicSharedMemorySize, AGG_SMEM);
    cudaFuncSetAttribute(k_gemm, cudaFuncAttributeMaxDynamicSharedMemorySize, GEMM_SMEM);

    k_embinit<<< 128, 128 >>> (emb, W1, out, out_size);
    k_prepB <<< 16, 256 >>> (W2);
    k_agg   <<< nG, 1024, AGG_SMEM >>> (feat, b1, (const int4*)src, (const int4*)dst, epg4);
    k_gemm  <<< n / 128, 256, GEMM_SMEM >>> (b2, out);   // 4th launch: profiled
}

// round 14
// speedup vs baseline: 2.2714x; 1.2429x over previous
#include <cuda_runtime.h>
#include <cuda_fp16.h>
#include <cstdint>

// Problem constants (B=256 graphs, N=512 nodes/graph, D=128, T=64)
#define NT   131072
#define NTC2 48              // CSR capacity per node (mean in-deg 16, ~8 sigma)
#define DD   128
#define TT   64
#define NPG  512
#define LOG2NPG 9

// ---------------- device scratch (static, no allocation) ----------------
__device__ __align__(16) __half g_Ph[TT * DD];              // emb_table @ W1, fp16
__device__ __align__(16) __half g_ah[(size_t)NT * DD];      // a = invin * sum x, fp16
__device__ __align__(16) uint2  g_Bfh[4096];                // W2 hi, mma-fragment order
__device__ __align__(16) uint2  g_Bfl[4096];                // W2 lo residual, same order
__device__ __align__(16) uint2  g_Pfrag[2048];              // P fragments (k=64)

// ---------------- helpers ----------------
__device__ __forceinline__ uint32_t s2u(const void* p) {
    uint32_t a;
    asm("{ .reg .u64 t; cvta.to.shared.u64 t, %1; cvt.u32.u64 %0, t; }" : "=r"(a) : "l"(p));
    return a;
}
__device__ __forceinline__ __half2 u2h(uint32_t v) { return *(__half2*)&v; }

__device__ __forceinline__ void ldsm_x4(uint32_t& r0, uint32_t& r1, uint32_t& r2,
                                        uint32_t& r3, uint32_t saddr) {
    asm volatile("ldmatrix.sync.aligned.m8n8.x4.shared.b16 {%0,%1,%2,%3}, [%4];"
                 : "=r"(r0), "=r"(r1), "=r"(r2), "=r"(r3) : "r"(saddr));
}
__device__ __forceinline__ void mma16(float c[4], uint32_t a0, uint32_t a1,
                                      uint32_t a2, uint32_t a3,
                                      uint32_t b0, uint32_t b1) {
    asm volatile(
        "mma.sync.aligned.m16n8k16.row.col.f32.f16.f16.f32 "
        "{%0,%1,%2,%3},{%4,%5,%6,%7},{%8,%9},{%0,%1,%2,%3};"
        : "+f"(c[0]), "+f"(c[1]), "+f"(c[2]), "+f"(c[3])
        : "r"(a0), "r"(a1), "r"(a2), "r"(a3), "r"(b0), "r"(b1));
}

// ---------------- kernels ----------------

// blocks 0..63: P = emb_table @ W1 -> fp16. blocks 64..127: zero out.
__global__ void k_embinit(const float* __restrict__ emb, const float* __restrict__ W1,
                          float* __restrict__ out, int out_size) {
    int b = blockIdx.x;
    if (b < TT) {
        __shared__ float er[DD];
        int d = threadIdx.x;
        er[d] = emb[b * DD + d];
        __syncthreads();
        float s = 0.0f;
        #pragma unroll 8
        for (int k = 0; k < DD; k++) s = fmaf(er[k], W1[k * DD + d], s);
        g_Ph[b * DD + d] = __float2half(s);
    } else {
        int idx = (b - TT) * DD + threadIdx.x;
        for (int i = idx; i < out_size; i += TT * DD) out[i] = 0.0f;
    }
}

// Pack W2 into per-lane mma B-fragment order, hi/lo fp16 split. (proven)
__global__ void k_prepB(const float* __restrict__ W2) {
    int i = blockIdx.x * blockDim.x + threadIdx.x;   // 4096
    int lane = i & 31, nt = (i >> 5) & 15, ks = i >> 9;
    int n = nt * 8 + (lane >> 2);
    int k0 = ks * 16 + 2 * (lane & 3);
    float w00 = W2[k0 * DD + n],       w01 = W2[(k0 + 1) * DD + n];
    float w10 = W2[(k0 + 8) * DD + n], w11 = W2[(k0 + 9) * DD + n];
    __half h00 = __float2half_rn(w00), h01 = __float2half_rn(w01);
    __half h10 = __float2half_rn(w10), h11 = __float2half_rn(w11);
    __half l00 = __float2half_rn(w00 - __half2float(h00));
    __half l01 = __float2half_rn(w01 - __half2float(h01));
    __half l10 = __float2half_rn(w10 - __half2float(h10));
    __half l11 = __float2half_rn(w11 - __half2float(h11));
    __half2 bh0 = __halves2half2(h00, h01), bh1 = __halves2half2(h10, h11);
    __half2 bl0 = __halves2half2(l00, l01), bl1 = __halves2half2(l10, l11);
    g_Bfh[i] = make_uint2(*(uint32_t*)&bh0, *(uint32_t*)&bh1);
    g_Bfl[i] = make_uint2(*(uint32_t*)&bl0, *(uint32_t*)&bl1);
}

// Pack P (fp16 [64][128]) into mma B-fragment order, k=64 (4 ks chunks).
__global__ void k_prepP() {
    int i = blockIdx.x * blockDim.x + threadIdx.x;   // 2048
    int lane = i & 31, nt = (i >> 5) & 15, ks = i >> 9;
    int n = nt * 8 + (lane >> 2);
    int k0 = ks * 16 + 2 * (lane & 3);
    __half2 b0 = __halves2half2(g_Ph[k0 * DD + n], g_Ph[(k0 + 1) * DD + n]);
    __half2 b1 = __halves2half2(g_Ph[(k0 + 8) * DD + n], g_Ph[(k0 + 9) * DD + n]);
    g_Pfrag[i] = make_uint2(*(uint32_t*)&b0, *(uint32_t*)&b1);
}

// Fully fused per-graph kernel, one CTA per graph (1024 threads).
// Stage A : build local CSR + degrees (smem atomics).
// Stage A2: Cw[v][t] = sum of wo[u] over in-edges (u of type t) -- fp16 atomics.
// Stage B : x = wo * relu(inv * (Cw @ P) + b1) via mma m16n8k16 (A=Cw ldmatrix,
//           B=g_Pfrag from global). Cw and x ALIAS one region: all A fragments
//           are read into registers before the barrier that precedes x writes.
// Stage C : a[v] = inv * sum x[u]  (half2 tree)  -> global fp16.
#define AGB_CSR 0                          // 49152
#define AGB_R   49152                      // x: 513 rows x 272B = 139536 (Cw aliases: 512 x 144B)
#define AGB_FT  188688                     // u8[512]
#define AGB_WOH 189200                     // u16[513] -> 1040
#define AGB_WO  190240                     // f32[513] -> 2064
#define AGB_INV 192304                     // 2048
#define AGB_CNT 194352                     // 2048
#define AGB_DEG 196400                     // 2048
#define AGB_B1  198448                     // 512
#define AGG_SMEM 198960
#define XSTR 34                            // x row stride in uint2 (272B)
__global__ void __launch_bounds__(1024, 1) k_agg(const int* __restrict__ feat,
                                                 const float* __restrict__ b1,
                                                 const int4* __restrict__ src4,
                                                 const int4* __restrict__ dst4,
                                                 int epg4) {
    extern __shared__ char sm[];
    unsigned short* s_csr = (unsigned short*)(sm + AGB_CSR);
    uint2*  s_x   = (uint2*)(sm + AGB_R);
    __half* s_cw  = (__half*)(sm + AGB_R);       // aliased, stride 72 halves (144B)
    unsigned char* s_ft = (unsigned char*)(sm + AGB_FT);
    unsigned short* s_woh = (unsigned short*)(sm + AGB_WOH);
    float*  s_wo  = (float*)(sm + AGB_WO);
    float*  s_inv = (float*)(sm + AGB_INV);
    int*    s_cnt = (int*)(sm + AGB_CNT);
    int*    s_deg = (int*)(sm + AGB_DEG);
    float*  s_b1f = (float*)(sm + AGB_B1);

    int tid = threadIdx.x, lane = tid & 31, w = tid >> 5;
    int g = blockIdx.x, vbase = g << LOG2NPG;

    if (tid < NPG) {
        s_cnt[tid] = 0; s_deg[tid] = 0;
        s_ft[tid] = (unsigned char)feat[vbase + tid];
    }
    if (tid < DD) s_b1f[tid] = b1[tid];
    {   // zero Cw region (512 x 72 halves = 73728 bytes = 4608 uint4)
        uint4 z = make_uint4(0u, 0u, 0u, 0u);
        uint4* cz = (uint4*)(sm + AGB_R);
        #pragma unroll
        for (int l = 0; l < 5; l++) {
            int i = tid + l * 1024;
            if (i < 4608) cz[i] = z;
        }
    }
    __syncthreads();

    // ---- stage A: CSR + degrees ----
    const int4* sp = src4 + (size_t)g * epg4;
    const int4* dp = dst4 + (size_t)g * epg4;
    for (int i = tid; i < epg4; i += 1024) {
        int4 s = sp[i], d = dp[i];
        int sl, dl, p;
        sl = s.x & (NPG - 1); dl = d.x & (NPG - 1);
        atomicAdd(&s_deg[sl], 1);
        p = atomicAdd(&s_cnt[dl], 1);
        if (p < NTC2) s_csr[dl * NTC2 + p] = (unsigned short)sl;
        sl = s.y & (NPG - 1); dl = d.y & (NPG - 1);
        atomicAdd(&s_deg[sl], 1);
        p = atomicAdd(&s_cnt[dl], 1);
        if (p < NTC2) s_csr[dl * NTC2 + p] = (unsigned short)sl;
        sl = s.z & (NPG - 1); dl = d.z & (NPG - 1);
        atomicAdd(&s_deg[sl], 1);
        p = atomicAdd(&s_cnt[dl], 1);
        if (p < NTC2) s_csr[dl * NTC2 + p] = (unsigned short)sl;
        sl = s.w & (NPG - 1); dl = d.w & (NPG - 1);
        atomicAdd(&s_deg[sl], 1);
        p = atomicAdd(&s_cnt[dl], 1);
        if (p < NTC2) s_csr[dl * NTC2 + p] = (unsigned short)sl;
    }
    __syncthreads();

    if (tid < NPG) {
        int draw = s_cnt[tid];
        int dq = s_deg[tid];
        int di = draw > NTC2 ? NTC2 : draw;
        int c4 = (di + 3) & ~3;
        for (int p = di; p < c4; p++) s_csr[tid * NTC2 + p] = (unsigned short)NPG;
        s_cnt[tid] = c4;
        float wo = rsqrtf((float)(dq > 1 ? dq : 1));
        s_wo[tid] = wo;
        __half wh = __float2half_rn(wo);
        s_woh[tid] = *(unsigned short*)&wh;
        s_inv[tid] = rsqrtf((float)(draw > 1 ? draw : 1));
    }
    __syncthreads();

    // ---- stage A2: Cw histogram (fp16 smem atomics) ----
    for (int i = tid; i < epg4; i += 1024) {
        int4 s = sp[i], d = dp[i];
        #pragma unroll
        for (int c = 0; c < 4; c++) {
            int sl = ((const int*)&s)[c] & (NPG - 1);
            int dl = ((const int*)&d)[c] & (NPG - 1);
            unsigned short wv = s_woh[sl];
            int t = s_ft[sl];
            atomicAdd(&s_cw[dl * 72 + t], *(__half*)&wv);
        }
    }
    __syncthreads();

    // ---- stage B: x = wo*relu(inv*(Cw@P) + b1) via mma ----
    // warp w owns rows 16w..16w+15. Read ALL A fragments first (Cw dies here).
    uint32_t a[16];
    {
        uint32_t aBase = s2u(sm + AGB_R)
                       + (uint32_t)(w * 16 + (lane & 15)) * 144 + ((lane >> 4) << 4);
        #pragma unroll
        for (int ks = 0; ks < 4; ks++)
            ldsm_x4(a[ks * 4], a[ks * 4 + 1], a[ks * 4 + 2], a[ks * 4 + 3],
                    aBase + ks * 32);
    }
    __syncthreads();        // all Cw reads complete before any x write

    int r_lo = w * 16 + (lane >> 2);
    float wol = s_wo[r_lo], wohf = s_wo[r_lo + 8];
    float invl = s_inv[r_lo], invh = s_inv[r_lo + 8];
    uint32_t xb = s2u(sm + AGB_R);

    #pragma unroll
    for (int q = 0; q < 4; q++) {           // 4 col-quarters of 32 cols
        float c[4][4];
        #pragma unroll
        for (int j = 0; j < 4; j++)
            #pragma unroll
            for (int e = 0; e < 4; e++) c[j][e] = 0.f;
        #pragma unroll
        for (int ks = 0; ks < 4; ks++) {
            #pragma unroll
            for (int j = 0; j < 4; j++) {
                uint2 f = g_Pfrag[(ks * 16 + q * 4 + j) * 32 + lane];
                mma16(c[j], a[ks * 4], a[ks * 4 + 1], a[ks * 4 + 2], a[ks * 4 + 3],
                      f.x, f.y);
            }
        }
        #pragma unroll
        for (int j = 0; j < 4; j++) {
            int col = (q * 4 + j) * 8 + 2 * (lane & 3);
            float b10 = s_b1f[col], b11 = s_b1f[col + 1];
            __half2 lo = __floats2half2_rn(
                wol * fmaxf(fmaf(invl, c[j][0], b10), 0.f),
                wol * fmaxf(fmaf(invl, c[j][1], b11), 0.f));
            __half2 hi = __floats2half2_rn(
                wohf * fmaxf(fmaf(invh, c[j][2], b10), 0.f),
                wohf * fmaxf(fmaf(invh, c[j][3], b11), 0.f));
            *(uint32_t*)(sm + AGB_R + r_lo * 272 + col * 2) = *(uint32_t*)&lo;
            *(uint32_t*)(sm + AGB_R + (r_lo + 8) * 272 + col * 2) = *(uint32_t*)&hi;
        }
    }
    if (tid < 32) s_x[NPG * XSTR + tid] = make_uint2(0u, 0u);   // sentinel row
    __syncthreads();

    // ---- stage C: aggregate x (half2 tree), write a (fp16) to global ----
    #pragma unroll 1
    for (int s = 0; s < 16; s++) {
        int lv = (w << 4) + s;
        int cnt = s_cnt[lv];
        const unsigned short* row = s_csr + lv * NTC2;
        float4 acc = make_float4(0.f, 0.f, 0.f, 0.f);
        for (int base = 0; base < cnt; base += 32) {
            int m = cnt - base; if (m > 32) m = 32;
            int ul = (lane < m) ? row[base + lane] : NPG;
            for (int j = 0; j < m; j += 4) {
                int u0 = __shfl_sync(0xffffffffu, ul, j);
                int u1 = __shfl_sync(0xffffffffu, ul, j + 1);
                int u2 = __shfl_sync(0xffffffffu, ul, j + 2);
                int u3 = __shfl_sync(0xffffffffu, ul, j + 3);
                uint2 q0 = s_x[u0 * XSTR + lane];
                uint2 q1 = s_x[u1 * XSTR + lane];
                uint2 q2 = s_x[u2 * XSTR + lane];
                uint2 q3 = s_x[u3 * XSTR + lane];
                __half2 sa = __hadd2(__hadd2(u2h(q0.x), u2h(q1.x)),
                                     __hadd2(u2h(q2.x), u2h(q3.x)));
                __half2 sb = __hadd2(__hadd2(u2h(q0.y), u2h(q1.y)),
                                     __hadd2(u2h(q2.y), u2h(q3.y)));
                float2 fa = __half22float2(sa);
                float2 fb = __half22float2(sb);
                acc.x += fa.x; acc.y += fa.y; acc.z += fb.x; acc.w += fb.y;
            }
        }
        float wi = s_inv[lv];
        __half2 q0 = __floats2half2_rn(wi * acc.x, wi * acc.y);
        __half2 q1 = __floats2half2_rn(wi * acc.z, wi * acc.w);
        uint2 st;
        st.x = *(uint32_t*)&q0;
        st.y = *(uint32_t*)&q1;
        ((uint2*)g_ah)[(size_t)(vbase + lv) * 32 + lane] = st;
    }
}

// Tensor-core GEMM (round-13, measured 30.5us) + fused epilogue.
#define GS_A   0
#define GS_BH  34816
#define GS_BL  67584
#define GS_COL 100352
#define GS_B2  100864
#define GEMM_SMEM 101376
__global__ void __launch_bounds__(256, 2) k_gemm(const float* __restrict__ b2,
                                                 float* __restrict__ out) {
    extern __shared__ char smraw[];
    uint2* smA2  = (uint2*)(smraw + GS_A);
    uint2* sBfh  = (uint2*)(smraw + GS_BH);
    uint2* sBfl  = (uint2*)(smraw + GS_BL);
    float* s_col = (float*)(smraw + GS_COL);
    float* s_b2  = (float*)(smraw + GS_B2);

    int tid = threadIdx.x, lane = tid & 31, w = tid >> 5;
    int row0 = blockIdx.x * 128;

    if (tid < DD) s_b2[tid] = b2[tid];

    {
        const uint2* A2 = (const uint2*)g_ah + (size_t)row0 * 32;
        #pragma unroll
        for (int l = 0; l < 16; l++) {
            int i = tid + l * 256;
            int r = i >> 5, c = i & 31;
            smA2[r * 34 + c] = A2[r * 32 + c];
        }
    }
    #pragma unroll
    for (int l = 0; l < 16; l++) {
        int i = tid + l * 256;
        sBfh[i] = g_Bfh[i];
        sBfl[i] = g_Bfl[i];
    }
    __syncthreads();

    float c[2][8][4];
    #pragma unroll
    for (int j = 0; j < 2; j++)
        #pragma unroll
        for (int mt = 0; mt < 8; mt++)
            #pragma unroll
            for (int q = 0; q < 4; q++) c[j][mt][q] = 0.f;

    uint32_t aBase = s2u(smraw) + (uint32_t)(lane & 15) * 272 + ((lane >> 4) << 4);
    int nt0 = 2 * w;

    #pragma unroll
    for (int ks = 0; ks < 8; ks++) {
        uint2 fh0 = sBfh[(ks * 16 + nt0) * 32 + lane];
        uint2 fh1 = sBfh[(ks * 16 + nt0 + 1) * 32 + lane];
        uint2 fl0 = sBfl[(ks * 16 + nt0) * 32 + lane];
        uint2 fl1 = sBfl[(ks * 16 + nt0 + 1) * 32 + lane];
        #pragma unroll
        for (int mt = 0; mt < 8; mt++) {
            uint32_t a0, a1, a2, a3;
            ldsm_x4(a0, a1, a2, a3, aBase + (uint32_t)(mt * 16 * 272 + ks * 32));
            mma16(c[0][mt], a0, a1, a2, a3, fh0.x, fh0.y);
            mma16(c[0][mt], a0, a1, a2, a3, fl0.x, fl0.y);
            mma16(c[1][mt], a0, a1, a2, a3, fh1.x, fh1.y);
            mma16(c[1][mt], a0, a1, a2, a3, fl1.x, fl1.y);
        }
    }

    int t = lane & 3;
    #pragma unroll
    for (int j = 0; j < 2; j++) {
        int colb = (nt0 + j) * 8 + 2 * t;
        float b20 = s_b2[colb], b21 = s_b2[colb + 1];
        float s0 = 0.f, s1 = 0.f;
        #pragma unroll
        for (int mt = 0; mt < 8; mt++) {
            s0 += fmaxf(c[j][mt][0] + b20, 0.f) + fmaxf(c[j][mt][2] + b20, 0.f);
            s1 += fmaxf(c[j][mt][1] + b21, 0.f) + fmaxf(c[j][mt][3] + b21, 0.f);
        }
        s0 += __shfl_xor_sync(0xffffffffu, s0, 4);
        s1 += __shfl_xor_sync(0xffffffffu, s1, 4);
        s0 += __shfl_xor_sync(0xffffffffu, s0, 8);
        s1 += __shfl_xor_sync(0xffffffffu, s1, 8);
        s0 += __shfl_xor_sync(0xffffffffu, s0, 16);
        s1 += __shfl_xor_sync(0xffffffffu, s1, 16);
        if (lane < 4) {
            s_col[colb] = s0;
            s_col[colb + 1] = s1;
        }
    }
    __syncthreads();
    if (tid < DD)
        atomicAdd(&out[(size_t)(row0 >> LOG2NPG) * DD + tid],
                  s_col[tid] * (1.0f / 512.0f));
}

// ---------------- launch ----------------
extern "C" void kernel_launch(void* const* d_in, const int* in_sizes, int n_in,
                              void* d_out, int out_size) {
    const int*   feat = (const int*)d_in[0];
    const int*   src  = (const int*)d_in[1];
    const int*   dst  = (const int*)d_in[2];
    const float* emb  = (const float*)d_in[3];
    const float* W1   = (const float*)d_in[4];
    const float* b1   = (const float*)d_in[5];
    const float* W2   = (const float*)d_in[6];
    const float* b2   = (const float*)d_in[7];
    float* out = (float*)d_out;

    int n = in_sizes[0];          // 131072
    int E = in_sizes[1];          // 2097152
    int nG = n >> LOG2NPG;        // 256 graphs
    int epg4 = (E / nG) >> 2;     // 2048 int4 per graph

    cudaFuncSetAttribute(k_agg, cudaFuncAttributeMaxDynamicSharedMemorySize, AGG_SMEM);
    cudaFuncSetAttribute(k_gemm, cudaFuncAttributeMaxDynamicSharedMemorySize, GEMM_SMEM);

    k_embinit<<< 128, 128 >>> (emb, W1, out, out_size);
    k_prepB <<< 16, 256 >>> (W2);
    k_prepP <<< 8, 256 >>> ();
    k_agg   <<< nG, 1024, AGG_SMEM >>> (feat, b1, (const int4*)src, (const int4*)dst, epg4);
    k_gemm  <<< n / 128, 256, GEMM_SMEM >>> (b2, out);
}

// round 15
// speedup vs baseline: 2.7659x; 1.2177x over previous
#include <cuda_runtime.h>
#include <cuda_fp16.h>
#include <cstdint>

// Problem constants (B=256 graphs, N=512 nodes/graph, D=128, T=64)
#define NT   131072
#define NTC2 48              // CSR capacity per node (mean in-deg 16, ~8 sigma)
#define DD   128
#define TT   64
#define NPG  512
#define LOG2NPG 9

// ---------------- device scratch (static, no allocation) ----------------
__device__ __align__(16) __half g_Ph[TT * DD];              // emb_table @ W1, fp16
__device__ __align__(16) __half g_ah[(size_t)NT * DD];      // a = invin * sum x, fp16
__device__ __align__(16) uint2  g_Bfh[4096];                // W2 fp16, mma-fragment order
__device__ __align__(16) uint2  g_Pfrag[2048];              // P fragments (k=64)

// ---------------- helpers ----------------
__device__ __forceinline__ uint32_t s2u(const void* p) {
    uint32_t a;
    asm("{ .reg .u64 t; cvta.to.shared.u64 t, %1; cvt.u32.u64 %0, t; }" : "=r"(a) : "l"(p));
    return a;
}
__device__ __forceinline__ __half2 u2h(uint32_t v) { return *(__half2*)&v; }

__device__ __forceinline__ void ldsm_x4(uint32_t& r0, uint32_t& r1, uint32_t& r2,
                                        uint32_t& r3, uint32_t saddr) {
    asm volatile("ldmatrix.sync.aligned.m8n8.x4.shared.b16 {%0,%1,%2,%3}, [%4];"
                 : "=r"(r0), "=r"(r1), "=r"(r2), "=r"(r3) : "r"(saddr));
}
__device__ __forceinline__ void mma16(float c[4], uint32_t a0, uint32_t a1,
                                      uint32_t a2, uint32_t a3,
                                      uint32_t b0, uint32_t b1) {
    asm volatile(
        "mma.sync.aligned.m16n8k16.row.col.f32.f16.f16.f32 "
        "{%0,%1,%2,%3},{%4,%5,%6,%7},{%8,%9},{%0,%1,%2,%3};"
        : "+f"(c[0]), "+f"(c[1]), "+f"(c[2]), "+f"(c[3])
        : "r"(a0), "r"(a1), "r"(a2), "r"(a3), "r"(b0), "r"(b1));
}

// ---------------- kernels ----------------

// blocks 0..63: P = emb_table @ W1 -> fp16. blocks 64..127: zero out.
__global__ void k_embinit(const float* __restrict__ emb, const float* __restrict__ W1,
                          float* __restrict__ out, int out_size) {
    int b = blockIdx.x;
    if (b < TT) {
        __shared__ float er[DD];
        int d = threadIdx.x;
        er[d] = emb[b * DD + d];
        __syncthreads();
        float s = 0.0f;
        #pragma unroll 8
        for (int k = 0; k < DD; k++) s = fmaf(er[k], W1[k * DD + d], s);
        g_Ph[b * DD + d] = __float2half(s);
    } else {
        int idx = (b - TT) * DD + threadIdx.x;
        for (int i = idx; i < out_size; i += TT * DD) out[i] = 0.0f;
    }
}

// blocks 0..15: W2 -> mma B-fragment order (fp16, no residual).
// blocks 16..23: P fragments (reads g_Ph written by the previous launch).
__global__ void k_prep(const float* __restrict__ W2) {
    int b = blockIdx.x;
    if (b < 16) {
        int i = b * 256 + threadIdx.x;               // 4096
        int lane = i & 31, nt = (i >> 5) & 15, ks = i >> 9;
        int n = nt * 8 + (lane >> 2);
        int k0 = ks * 16 + 2 * (lane & 3);
        __half2 bh0 = __floats2half2_rn(W2[k0 * DD + n], W2[(k0 + 1) * DD + n]);
        __half2 bh1 = __floats2half2_rn(W2[(k0 + 8) * DD + n], W2[(k0 + 9) * DD + n]);
        g_Bfh[i] = make_uint2(*(uint32_t*)&bh0, *(uint32_t*)&bh1);
    } else {
        int i = (b - 16) * 256 + threadIdx.x;        // 2048
        int lane = i & 31, nt = (i >> 5) & 15, ks = i >> 9;
        int n = nt * 8 + (lane >> 2);
        int k0 = ks * 16 + 2 * (lane & 3);
        __half2 b0 = __halves2half2(g_Ph[k0 * DD + n], g_Ph[(k0 + 1) * DD + n]);
        __half2 b1 = __halves2half2(g_Ph[(k0 + 8) * DD + n], g_Ph[(k0 + 9) * DD + n]);
        g_Pfrag[i] = make_uint2(*(uint32_t*)&b0, *(uint32_t*)&b1);
    }
}

// Fully fused per-graph kernel, one CTA per graph (1024 threads).
// Stage A : build local CSR + degrees (smem atomics); edges cached in regs.
// Stage A2: Cw[v][t] = sum wo[u] over in-edges of type t (fp16 smem atomics).
// Stage B : x = wo * relu(inv * (Cw @ P) + b1) via mma (Cw/x alias one region).
// Stage C : a[v] = inv * sum x[u]  (ushort4 index broadcast, half2 tree).
#define AGB_CSR 0                          // 49152
#define AGB_R   49152                      // x: 513 x 272B = 139536 (Cw aliases: 512 x 144B)
#define AGB_FT  188688                     // u8[512]
#define AGB_WOH 189200                     // u16[513] -> 1040
#define AGB_WO  190240                     // f32[513] -> 2064
#define AGB_INV 192304                     // 2048
#define AGB_CNT 194352                     // 2048
#define AGB_DEG 196400                     // 2048
#define AGB_B1  198448                     // 512
#define AGG_SMEM 198960
#define XSTR 34                            // x row stride in uint2 (272B)
__global__ void __launch_bounds__(1024, 1) k_agg(const int* __restrict__ feat,
                                                 const float* __restrict__ b1,
                                                 const int4* __restrict__ src4,
                                                 const int4* __restrict__ dst4,
                                                 int epg4) {
    extern __shared__ char sm[];
    unsigned short* s_csr = (unsigned short*)(sm + AGB_CSR);
    uint2*  s_x   = (uint2*)(sm + AGB_R);
    __half* s_cw  = (__half*)(sm + AGB_R);       // aliased, stride 72 halves (144B)
    unsigned char* s_ft = (unsigned char*)(sm + AGB_FT);
    unsigned short* s_woh = (unsigned short*)(sm + AGB_WOH);
    float*  s_wo  = (float*)(sm + AGB_WO);
    float*  s_inv = (float*)(sm + AGB_INV);
    int*    s_cnt = (int*)(sm + AGB_CNT);
    int*    s_deg = (int*)(sm + AGB_DEG);
    float*  s_b1f = (float*)(sm + AGB_B1);

    int tid = threadIdx.x, lane = tid & 31, w = tid >> 5;
    int g = blockIdx.x, vbase = g << LOG2NPG;

    if (tid < NPG) {
        s_cnt[tid] = 0; s_deg[tid] = 0;
        s_ft[tid] = (unsigned char)feat[vbase + tid];
    }
    if (tid < DD) s_b1f[tid] = b1[tid];
    {   // zero Cw region (512 x 72 halves = 73728 bytes = 4608 uint4)
        uint4 z = make_uint4(0u, 0u, 0u, 0u);
        uint4* cz = (uint4*)(sm + AGB_R);
        #pragma unroll
        for (int l = 0; l < 5; l++) {
            int i = tid + l * 1024;
            if (i < 4608) cz[i] = z;
        }
    }
    // load this thread's edge slice into registers (epg4 = 2048 -> 2 per thread)
    const int4* sp = src4 + (size_t)g * epg4;
    const int4* dp = dst4 + (size_t)g * epg4;
    int4 es[2], ed[2];
    int ne = 0;
    if (tid < epg4)        { es[0] = sp[tid];        ed[0] = dp[tid];        ne = 1; }
    if (tid + 1024 < epg4) { es[1] = sp[tid + 1024]; ed[1] = dp[tid + 1024]; ne = 2; }
    __syncthreads();

    // ---- stage A: CSR + degrees ----
    for (int i = 0; i < ne; i++) {
        int4 s = es[i], d = ed[i];
        int sl, dl, p;
        sl = s.x & (NPG - 1); dl = d.x & (NPG - 1);
        atomicAdd(&s_deg[sl], 1);
        p = atomicAdd(&s_cnt[dl], 1);
        if (p < NTC2) s_csr[dl * NTC2 + p] = (unsigned short)sl;
        sl = s.y & (NPG - 1); dl = d.y & (NPG - 1);
        atomicAdd(&s_deg[sl], 1);
        p = atomicAdd(&s_cnt[dl], 1);
        if (p < NTC2) s_csr[dl * NTC2 + p] = (unsigned short)sl;
        sl = s.z & (NPG - 1); dl = d.z & (NPG - 1);
        atomicAdd(&s_deg[sl], 1);
        p = atomicAdd(&s_cnt[dl], 1);
        if (p < NTC2) s_csr[dl * NTC2 + p] = (unsigned short)sl;
        sl = s.w & (NPG - 1); dl = d.w & (NPG - 1);
        atomicAdd(&s_deg[sl], 1);
        p = atomicAdd(&s_cnt[dl], 1);
        if (p < NTC2) s_csr[dl * NTC2 + p] = (unsigned short)sl;
    }
    __syncthreads();

    if (tid < NPG) {
        int draw = s_cnt[tid];
        int dq = s_deg[tid];
        int di = draw > NTC2 ? NTC2 : draw;
        int c4 = (di + 3) & ~3;
        for (int p = di; p < c4; p++) s_csr[tid * NTC2 + p] = (unsigned short)NPG;
        s_cnt[tid] = c4;
        float wo = rsqrtf((float)(dq > 1 ? dq : 1));
        s_wo[tid] = wo;
        __half wh = __float2half_rn(wo);
        s_woh[tid] = *(unsigned short*)&wh;
        s_inv[tid] = rsqrtf((float)(draw > 1 ? draw : 1));
    }
    __syncthreads();

    // ---- stage A2: Cw histogram (fp16 smem atomics, edges from regs) ----
    for (int i = 0; i < ne; i++) {
        int4 s = es[i], d = ed[i];
        #pragma unroll
        for (int c = 0; c < 4; c++) {
            int sl = ((const int*)&s)[c] & (NPG - 1);
            int dl = ((const int*)&d)[c] & (NPG - 1);
            unsigned short wv = s_woh[sl];
            int t = s_ft[sl];
            atomicAdd(&s_cw[dl * 72 + t], *(__half*)&wv);
        }
    }
    __syncthreads();

    // ---- stage B: x = wo*relu(inv*(Cw@P) + b1) via mma ----
    uint32_t a[16];
    {
        uint32_t aBase = s2u(sm + AGB_R)
                       + (uint32_t)(w * 16 + (lane & 15)) * 144 + ((lane >> 4) << 4);
        #pragma unroll
        for (int ks = 0; ks < 4; ks++)
            ldsm_x4(a[ks * 4], a[ks * 4 + 1], a[ks * 4 + 2], a[ks * 4 + 3],
                    aBase + ks * 32);
    }
    __syncthreads();        // all Cw reads complete before any x write

    int r_lo = w * 16 + (lane >> 2);
    float wol = s_wo[r_lo], wohf = s_wo[r_lo + 8];
    float invl = s_inv[r_lo], invh = s_inv[r_lo + 8];

    #pragma unroll
    for (int q = 0; q < 4; q++) {           // 4 col-quarters of 32 cols
        float c[4][4];
        #pragma unroll
        for (int j = 0; j < 4; j++)
            #pragma unroll
            for (int e = 0; e < 4; e++) c[j][e] = 0.f;
        #pragma unroll
        for (int ks = 0; ks < 4; ks++) {
            #pragma unroll
            for (int j = 0; j < 4; j++) {
                uint2 f = g_Pfrag[(ks * 16 + q * 4 + j) * 32 + lane];
                mma16(c[j], a[ks * 4], a[ks * 4 + 1], a[ks * 4 + 2], a[ks * 4 + 3],
                      f.x, f.y);
            }
        }
        #pragma unroll
        for (int j = 0; j < 4; j++) {
            int col = (q * 4 + j) * 8 + 2 * (lane & 3);
            float b10 = s_b1f[col], b11 = s_b1f[col + 1];
            __half2 lo = __floats2half2_rn(
                wol * fmaxf(fmaf(invl, c[j][0], b10), 0.f),
                wol * fmaxf(fmaf(invl, c[j][1], b11), 0.f));
            __half2 hi = __floats2half2_rn(
                wohf * fmaxf(fmaf(invh, c[j][2], b10), 0.f),
                wohf * fmaxf(fmaf(invh, c[j][3], b11), 0.f));
            *(uint32_t*)(sm + AGB_R + r_lo * 272 + col * 2) = *(uint32_t*)&lo;
            *(uint32_t*)(sm + AGB_R + (r_lo + 8) * 272 + col * 2) = *(uint32_t*)&hi;
        }
    }
    if (tid < 32) s_x[NPG * XSTR + tid] = make_uint2(0u, 0u);   // sentinel row
    __syncthreads();

    // ---- stage C: aggregate x (ushort4 index broadcast + half2 tree) ----
    #pragma unroll 1
    for (int s = 0; s < 16; s++) {
        int lv = (w << 4) + s;
        int cnt = s_cnt[lv];
        const unsigned short* row = s_csr + lv * NTC2;
        float4 acc = make_float4(0.f, 0.f, 0.f, 0.f);
        #pragma unroll 1
        for (int j = 0; j < cnt; j += 4) {
            ushort4 uu = *(const ushort4*)(row + j);   // broadcast LDS.64
            uint2 q0 = s_x[uu.x * XSTR + lane];
            uint2 q1 = s_x[uu.y * XSTR + lane];
            uint2 q2 = s_x[uu.z * XSTR + lane];
            uint2 q3 = s_x[uu.w * XSTR + lane];
            __half2 sa = __hadd2(__hadd2(u2h(q0.x), u2h(q1.x)),
                                 __hadd2(u2h(q2.x), u2h(q3.x)));
            __half2 sb = __hadd2(__hadd2(u2h(q0.y), u2h(q1.y)),
                                 __hadd2(u2h(q2.y), u2h(q3.y)));
            float2 fa = __half22float2(sa);
            float2 fb = __half22float2(sb);
            acc.x += fa.x; acc.y += fa.y; acc.z += fb.x; acc.w += fb.y;
        }
        float wi = s_inv[lv];
        __half2 q0 = __floats2half2_rn(wi * acc.x, wi * acc.y);
        __half2 q1 = __floats2half2_rn(wi * acc.z, wi * acc.w);
        uint2 st;
        st.x = *(uint32_t*)&q0;
        st.y = *(uint32_t*)&q1;
        ((uint2*)g_ah)[(size_t)(vbase + lv) * 32 + lane] = st;
    }
}

// Tensor-core GEMM (single fp16 B, no residual) + fused epilogue.
#define GS_A   0                            // 128 x 272B = 34816
#define GS_BH  34816                        // 32768
#define GS_COL 67584                        // 512
#define GS_B2  68096                        // 512
#define GEMM_SMEM 68608
__global__ void __launch_bounds__(256, 2) k_gemm(const float* __restrict__ b2,
                                                 float* __restrict__ out) {
    extern __shared__ char smraw[];
    uint2* smA2  = (uint2*)(smraw + GS_A);
    uint2* sBfh  = (uint2*)(smraw + GS_BH);
    float* s_col = (float*)(smraw + GS_COL);
    float* s_b2  = (float*)(smraw + GS_B2);

    int tid = threadIdx.x, lane = tid & 31, w = tid >> 5;
    int row0 = blockIdx.x * 128;

    if (tid < DD) s_b2[tid] = b2[tid];

    {
        const uint2* A2 = (const uint2*)g_ah + (size_t)row0 * 32;
        #pragma unroll
        for (int l = 0; l < 16; l++) {
            int i = tid + l * 256;
            int r = i >> 5, c = i & 31;
            smA2[r * 34 + c] = A2[r * 32 + c];
        }
    }
    #pragma unroll
    for (int l = 0; l < 16; l++) {
        int i = tid + l * 256;
        sBfh[i] = g_Bfh[i];
    }
    __syncthreads();

    float c[2][8][4];
    #pragma unroll
    for (int j = 0; j < 2; j++)
        #pragma unroll
        for (int mt = 0; mt < 8; mt++)
            #pragma unroll
            for (int q = 0; q < 4; q++) c[j][mt][q] = 0.f;

    uint32_t aBase = s2u(smraw) + (uint32_t)(lane & 15) * 272 + ((lane >> 4) << 4);
    int nt0 = 2 * w;

    #pragma unroll
    for (int ks = 0; ks < 8; ks++) {
        uint2 fh0 = sBfh[(ks * 16 + nt0) * 32 + lane];
        uint2 fh1 = sBfh[(ks * 16 + nt0 + 1) * 32 + lane];
        #pragma unroll
        for (int mt = 0; mt < 8; mt++) {
            uint32_t a0, a1, a2, a3;
            ldsm_x4(a0, a1, a2, a3, aBase + (uint32_t)(mt * 16 * 272 + ks * 32));
            mma16(c[0][mt], a0, a1, a2, a3, fh0.x, fh0.y);
            mma16(c[1][mt], a0, a1, a2, a3, fh1.x, fh1.y);
        }
    }

    int t = lane & 3;
    #pragma unroll
    for (int j = 0; j < 2; j++) {
        int colb = (nt0 + j) * 8 + 2 * t;
        float b20 = s_b2[colb], b21 = s_b2[colb + 1];
        float s0 = 0.f, s1 = 0.f;
        #pragma unroll
        for (int mt = 0; mt < 8; mt++) {
            s0 += fmaxf(c[j][mt][0] + b20, 0.f) + fmaxf(c[j][mt][2] + b20, 0.f);
            s1 += fmaxf(c[j][mt][1] + b21, 0.f) + fmaxf(c[j][mt][3] + b21, 0.f);
        }
        s0 += __shfl_xor_sync(0xffffffffu, s0, 4);
        s1 += __shfl_xor_sync(0xffffffffu, s1, 4);
        s0 += __shfl_xor_sync(0xffffffffu, s0, 8);
        s1 += __shfl_xor_sync(0xffffffffu, s1, 8);
        s0 += __shfl_xor_sync(0xffffffffu, s0, 16);
        s1 += __shfl_xor_sync(0xffffffffu, s1, 16);
        if (lane < 4) {
            s_col[colb] = s0;
            s_col[colb + 1] = s1;
        }
    }
    __syncthreads();
    if (tid < DD)
        atomicAdd(&out[(size_t)(row0 >> LOG2NPG) * DD + tid],
                  s_col[tid] * (1.0f / 512.0f));
}

// ---------------- launch ----------------
extern "C" void kernel_launch(void* const* d_in, const int* in_sizes, int n_in,
                              void* d_out, int out_size) {
    const int*   feat = (const int*)d_in[0];
    const int*   src  = (const int*)d_in[1];
    const int*   dst  = (const int*)d_in[2];
    const float* emb  = (const float*)d_in[3];
    const float* W1   = (const float*)d_in[4];
    const float* b1   = (const float*)d_in[5];
    const float* W2   = (const float*)d_in[6];
    const float* b2   = (const float*)d_in[7];
    float* out = (float*)d_out;

    int n = in_sizes[0];          // 131072
    int E = in_sizes[1];          // 2097152
    int nG = n >> LOG2NPG;        // 256 graphs
    int epg4 = (E / nG) >> 2;     // 2048 int4 per graph

    cudaFuncSetAttribute(k_agg, cudaFuncAttributeMaxDynamicSharedMemorySize, AGG_SMEM);
    cudaFuncSetAttribute(k_gemm, cudaFuncAttributeMaxDynamicSharedMemorySize, GEMM_SMEM);

    k_embinit<<< 128, 128 >>> (emb, W1, out, out_size);
    k_prep  <<< 24, 256 >>> (W2);
    k_agg   <<< nG, 1024, AGG_SMEM >>> (feat, b1, (const int4*)src, (const int4*)dst, epg4);
    k_gemm  <<< n / 128, 256, GEMM_SMEM >>> (b2, out);
}

// round 16
// speedup vs baseline: 2.8435x; 1.0280x over previous
#include <cuda_runtime.h>
#include <cuda_fp16.h>
#include <cstdint>

// Problem constants (B=256 graphs, N=512 nodes/graph, D=128, T=64)
#define NT   131072
#define NTC2 48              // CSR capacity per node (mean in-deg 16, ~8 sigma)
#define DD   128
#define TT   64
#define NPG  512
#define LOG2NPG 9

// ---------------- device scratch (static, no allocation) ----------------
__device__ __align__(16) __half g_Ph[TT * DD];              // emb_table @ W1, fp16
__device__ __align__(16) __half g_ah[(size_t)NT * DD];      // a = invin * sum x, fp16
__device__ __align__(16) uint2  g_Bfh[4096];                // W2 fp16, mma-fragment order
__device__ __align__(16) uint2  g_Pfrag[2048];              // P fragments (k=64)

// ---------------- helpers ----------------
__device__ __forceinline__ uint32_t s2u(const void* p) {
    uint32_t a;
    asm("{ .reg .u64 t; cvta.to.shared.u64 t, %1; cvt.u32.u64 %0, t; }" : "=r"(a) : "l"(p));
    return a;
}
__device__ __forceinline__ __half2 u2h(uint32_t v) { return *(__half2*)&v; }

__device__ __forceinline__ void ldsm_x4(uint32_t& r0, uint32_t& r1, uint32_t& r2,
                                        uint32_t& r3, uint32_t saddr) {
    asm volatile("ldmatrix.sync.aligned.m8n8.x4.shared.b16 {%0,%1,%2,%3}, [%4];"
                 : "=r"(r0), "=r"(r1), "=r"(r2), "=r"(r3) : "r"(saddr));
}
__device__ __forceinline__ void mma16(float c[4], uint32_t a0, uint32_t a1,
                                      uint32_t a2, uint32_t a3,
                                      uint32_t b0, uint32_t b1) {
    asm volatile(
        "mma.sync.aligned.m16n8k16.row.col.f32.f16.f16.f32 "
        "{%0,%1,%2,%3},{%4,%5,%6,%7},{%8,%9},{%0,%1,%2,%3};"
        : "+f"(c[0]), "+f"(c[1]), "+f"(c[2]), "+f"(c[3])
        : "r"(a0), "r"(a1), "r"(a2), "r"(a3), "r"(b0), "r"(b1));
}

// ---------------- kernels ----------------

// blocks 0..63: P = emb_table @ W1 -> fp16. blocks 64..127: zero out.
__global__ void k_embinit(const float* __restrict__ emb, const float* __restrict__ W1,
                          float* __restrict__ out, int out_size) {
    int b = blockIdx.x;
    if (b < TT) {
        __shared__ float er[DD];
        int d = threadIdx.x;
        er[d] = emb[b * DD + d];
        __syncthreads();
        float s = 0.0f;
        #pragma unroll 8
        for (int k = 0; k < DD; k++) s = fmaf(er[k], W1[k * DD + d], s);
        g_Ph[b * DD + d] = __float2half(s);
    } else {
        int idx = (b - TT) * DD + threadIdx.x;
        for (int i = idx; i < out_size; i += TT * DD) out[i] = 0.0f;
    }
}

// blocks 0..15: W2 -> mma B-fragment order (fp16). blocks 16..23: P fragments.
__global__ void k_prep(const float* __restrict__ W2) {
    int b = blockIdx.x;
    if (b < 16) {
        int i = b * 256 + threadIdx.x;               // 4096
        int lane = i & 31, nt = (i >> 5) & 15, ks = i >> 9;
        int n = nt * 8 + (lane >> 2);
        int k0 = ks * 16 + 2 * (lane & 3);
        __half2 bh0 = __floats2half2_rn(W2[k0 * DD + n], W2[(k0 + 1) * DD + n]);
        __half2 bh1 = __floats2half2_rn(W2[(k0 + 8) * DD + n], W2[(k0 + 9) * DD + n]);
        g_Bfh[i] = make_uint2(*(uint32_t*)&bh0, *(uint32_t*)&bh1);
    } else {
        int i = (b - 16) * 256 + threadIdx.x;        // 2048
        int lane = i & 31, nt = (i >> 5) & 15, ks = i >> 9;
        int n = nt * 8 + (lane >> 2);
        int k0 = ks * 16 + 2 * (lane & 3);
        __half2 b0 = __halves2half2(g_Ph[k0 * DD + n], g_Ph[(k0 + 1) * DD + n]);
        __half2 b1 = __halves2half2(g_Ph[(k0 + 8) * DD + n], g_Ph[(k0 + 9) * DD + n]);
        g_Pfrag[i] = make_uint2(*(uint32_t*)&b0, *(uint32_t*)&b1);
    }
}

// Fully fused per-graph kernel (unchanged from round 15).
#define AGB_CSR 0
#define AGB_R   49152
#define AGB_FT  188688
#define AGB_WOH 189200
#define AGB_WO  190240
#define AGB_INV 192304
#define AGB_CNT 194352
#define AGB_DEG 196400
#define AGB_B1  198448
#define AGG_SMEM 198960
#define XSTR 34
__global__ void __launch_bounds__(1024, 1) k_agg(const int* __restrict__ feat,
                                                 const float* __restrict__ b1,
                                                 const int4* __restrict__ src4,
                                                 const int4* __restrict__ dst4,
                                                 int epg4) {
    extern __shared__ char sm[];
    unsigned short* s_csr = (unsigned short*)(sm + AGB_CSR);
    uint2*  s_x   = (uint2*)(sm + AGB_R);
    __half* s_cw  = (__half*)(sm + AGB_R);
    unsigned char* s_ft = (unsigned char*)(sm + AGB_FT);
    unsigned short* s_woh = (unsigned short*)(sm + AGB_WOH);
    float*  s_wo  = (float*)(sm + AGB_WO);
    float*  s_inv = (float*)(sm + AGB_INV);
    int*    s_cnt = (int*)(sm + AGB_CNT);
    int*    s_deg = (int*)(sm + AGB_DEG);
    float*  s_b1f = (float*)(sm + AGB_B1);

    int tid = threadIdx.x, lane = tid & 31, w = tid >> 5;
    int g = blockIdx.x, vbase = g << LOG2NPG;

    if (tid < NPG) {
        s_cnt[tid] = 0; s_deg[tid] = 0;
        s_ft[tid] = (unsigned char)feat[vbase + tid];
    }
    if (tid < DD) s_b1f[tid] = b1[tid];
    {
        uint4 z = make_uint4(0u, 0u, 0u, 0u);
        uint4* cz = (uint4*)(sm + AGB_R);
        #pragma unroll
        for (int l = 0; l < 5; l++) {
            int i = tid + l * 1024;
            if (i < 4608) cz[i] = z;
        }
    }
    const int4* sp = src4 + (size_t)g * epg4;
    const int4* dp = dst4 + (size_t)g * epg4;
    int4 es[2], ed[2];
    int ne = 0;
    if (tid < epg4)        { es[0] = sp[tid];        ed[0] = dp[tid];        ne = 1; }
    if (tid + 1024 < epg4) { es[1] = sp[tid + 1024]; ed[1] = dp[tid + 1024]; ne = 2; }
    __syncthreads();

    for (int i = 0; i < ne; i++) {
        int4 s = es[i], d = ed[i];
        int sl, dl, p;
        sl = s.x & (NPG - 1); dl = d.x & (NPG - 1);
        atomicAdd(&s_deg[sl], 1);
        p = atomicAdd(&s_cnt[dl], 1);
        if (p < NTC2) s_csr[dl * NTC2 + p] = (unsigned short)sl;
        sl = s.y & (NPG - 1); dl = d.y & (NPG - 1);
        atomicAdd(&s_deg[sl], 1);
        p = atomicAdd(&s_cnt[dl], 1);
        if (p < NTC2) s_csr[dl * NTC2 + p] = (unsigned short)sl;
        sl = s.z & (NPG - 1); dl = d.z & (NPG - 1);
        atomicAdd(&s_deg[sl], 1);
        p = atomicAdd(&s_cnt[dl], 1);
        if (p < NTC2) s_csr[dl * NTC2 + p] = (unsigned short)sl;
        sl = s.w & (NPG - 1); dl = d.w & (NPG - 1);
        atomicAdd(&s_deg[sl], 1);
        p = atomicAdd(&s_cnt[dl], 1);
        if (p < NTC2) s_csr[dl * NTC2 + p] = (unsigned short)sl;
    }
    __syncthreads();

    if (tid < NPG) {
        int draw = s_cnt[tid];
        int dq = s_deg[tid];
        int di = draw > NTC2 ? NTC2 : draw;
        int c4 = (di + 3) & ~3;
        for (int p = di; p < c4; p++) s_csr[tid * NTC2 + p] = (unsigned short)NPG;
        s_cnt[tid] = c4;
        float wo = rsqrtf((float)(dq > 1 ? dq : 1));
        s_wo[tid] = wo;
        __half wh = __float2half_rn(wo);
        s_woh[tid] = *(unsigned short*)&wh;
        s_inv[tid] = rsqrtf((float)(draw > 1 ? draw : 1));
    }
    __syncthreads();

    for (int i = 0; i < ne; i++) {
        int4 s = es[i], d = ed[i];
        #pragma unroll
        for (int c = 0; c < 4; c++) {
            int sl = ((const int*)&s)[c] & (NPG - 1);
            int dl = ((const int*)&d)[c] & (NPG - 1);
            unsigned short wv = s_woh[sl];
            int t = s_ft[sl];
            atomicAdd(&s_cw[dl * 72 + t], *(__half*)&wv);
        }
    }
    __syncthreads();

    uint32_t a[16];
    {
        uint32_t aBase = s2u(sm + AGB_R)
                       + (uint32_t)(w * 16 + (lane & 15)) * 144 + ((lane >> 4) << 4);
        #pragma unroll
        for (int ks = 0; ks < 4; ks++)
            ldsm_x4(a[ks * 4], a[ks * 4 + 1], a[ks * 4 + 2], a[ks * 4 + 3],
                    aBase + ks * 32);
    }
    __syncthreads();

    int r_lo = w * 16 + (lane >> 2);
    float wol = s_wo[r_lo], wohf = s_wo[r_lo + 8];
    float invl = s_inv[r_lo], invh = s_inv[r_lo + 8];

    #pragma unroll
    for (int q = 0; q < 4; q++) {
        float c[4][4];
        #pragma unroll
        for (int j = 0; j < 4; j++)
            #pragma unroll
            for (int e = 0; e < 4; e++) c[j][e] = 0.f;
        #pragma unroll
        for (int ks = 0; ks < 4; ks++) {
            #pragma unroll
            for (int j = 0; j < 4; j++) {
                uint2 f = g_Pfrag[(ks * 16 + q * 4 + j) * 32 + lane];
                mma16(c[j], a[ks * 4], a[ks * 4 + 1], a[ks * 4 + 2], a[ks * 4 + 3],
                      f.x, f.y);
            }
        }
        #pragma unroll
        for (int j = 0; j < 4; j++) {
            int col = (q * 4 + j) * 8 + 2 * (lane & 3);
            float b10 = s_b1f[col], b11 = s_b1f[col + 1];
            __half2 lo = __floats2half2_rn(
                wol * fmaxf(fmaf(invl, c[j][0], b10), 0.f),
                wol * fmaxf(fmaf(invl, c[j][1], b11), 0.f));
            __half2 hi = __floats2half2_rn(
                wohf * fmaxf(fmaf(invh, c[j][2], b10), 0.f),
                wohf * fmaxf(fmaf(invh, c[j][3], b11), 0.f));
            *(uint32_t*)(sm + AGB_R + r_lo * 272 + col * 2) = *(uint32_t*)&lo;
            *(uint32_t*)(sm + AGB_R + (r_lo + 8) * 272 + col * 2) = *(uint32_t*)&hi;
        }
    }
    if (tid < 32) s_x[NPG * XSTR + tid] = make_uint2(0u, 0u);
    __syncthreads();

    #pragma unroll 1
    for (int s = 0; s < 16; s++) {
        int lv = (w << 4) + s;
        int cnt = s_cnt[lv];
        const unsigned short* row = s_csr + lv * NTC2;
        float4 acc = make_float4(0.f, 0.f, 0.f, 0.f);
        #pragma unroll 1
        for (int j = 0; j < cnt; j += 4) {
            ushort4 uu = *(const ushort4*)(row + j);
            uint2 q0 = s_x[uu.x * XSTR + lane];
            uint2 q1 = s_x[uu.y * XSTR + lane];
            uint2 q2 = s_x[uu.z * XSTR + lane];
            uint2 q3 = s_x[uu.w * XSTR + lane];
            __half2 sa = __hadd2(__hadd2(u2h(q0.x), u2h(q1.x)),
                                 __hadd2(u2h(q2.x), u2h(q3.x)));
            __half2 sb = __hadd2(__hadd2(u2h(q0.y), u2h(q1.y)),
                                 __hadd2(u2h(q2.y), u2h(q3.y)));
            float2 fa = __half22float2(sa);
            float2 fb = __half22float2(sb);
            acc.x += fa.x; acc.y += fa.y; acc.z += fb.x; acc.w += fb.y;
        }
        float wi = s_inv[lv];
        __half2 q0 = __floats2half2_rn(wi * acc.x, wi * acc.y);
        __half2 q1 = __floats2half2_rn(wi * acc.z, wi * acc.w);
        uint2 st;
        st.x = *(uint32_t*)&q0;
        st.y = *(uint32_t*)&q1;
        ((uint2*)g_ah)[(size_t)(vbase + lv) * 32 + lane] = st;
    }
}

// Tensor-core GEMM, high occupancy: B fragments read from global (L1),
// mtiles processed in 2 groups of 4 (32 acc regs), 3 CTAs/SM target.
#define GS_A   0                            // 128 x 272B = 34816
#define GS_COL 34816                        // 512
#define GS_B2  35328                        // 512
#define GEMM_SMEM 35840
__global__ void __launch_bounds__(256, 3) k_gemm(const float* __restrict__ b2,
                                                 float* __restrict__ out) {
    extern __shared__ char smraw[];
    uint2* smA2  = (uint2*)(smraw + GS_A);
    float* s_col = (float*)(smraw + GS_COL);
    float* s_b2  = (float*)(smraw + GS_B2);

    int tid = threadIdx.x, lane = tid & 31, w = tid >> 5;
    int row0 = blockIdx.x * 128;

    if (tid < DD) s_b2[tid] = b2[tid];

    {
        const uint2* A2 = (const uint2*)g_ah + (size_t)row0 * 32;
        #pragma unroll
        for (int l = 0; l < 16; l++) {
            int i = tid + l * 256;
            int r = i >> 5, c = i & 31;
            smA2[r * 34 + c] = A2[r * 32 + c];
        }
    }
    __syncthreads();

    uint32_t aBase = s2u(smraw) + (uint32_t)(lane & 15) * 272 + ((lane >> 4) << 4);
    int nt0 = 2 * w;
    int t = lane & 3;
    int colb0 = nt0 * 8 + 2 * t, colb1 = (nt0 + 1) * 8 + 2 * t;
    float b200 = s_b2[colb0], b201 = s_b2[colb0 + 1];
    float b210 = s_b2[colb1], b211 = s_b2[colb1 + 1];
    float s00 = 0.f, s01 = 0.f, s10 = 0.f, s11 = 0.f;

    #pragma unroll
    for (int mg = 0; mg < 2; mg++) {
        float c[2][4][4];
        #pragma unroll
        for (int j = 0; j < 2; j++)
            #pragma unroll
            for (int mt = 0; mt < 4; mt++)
                #pragma unroll
                for (int q = 0; q < 4; q++) c[j][mt][q] = 0.f;

        #pragma unroll
        for (int ks = 0; ks < 8; ks++) {
            uint2 fh0 = g_Bfh[(ks * 16 + nt0) * 32 + lane];
            uint2 fh1 = g_Bfh[(ks * 16 + nt0 + 1) * 32 + lane];
            #pragma unroll
            for (int mt = 0; mt < 4; mt++) {
                uint32_t a0, a1, a2, a3;
                ldsm_x4(a0, a1, a2, a3,
                        aBase + (uint32_t)((mg * 4 + mt) * 16 * 272 + ks * 32));
                mma16(c[0][mt], a0, a1, a2, a3, fh0.x, fh0.y);
                mma16(c[1][mt], a0, a1, a2, a3, fh1.x, fh1.y);
            }
        }
        #pragma unroll
        for (int mt = 0; mt < 4; mt++) {
            s00 += fmaxf(c[0][mt][0] + b200, 0.f) + fmaxf(c[0][mt][2] + b200, 0.f);
            s01 += fmaxf(c[0][mt][1] + b201, 0.f) + fmaxf(c[0][mt][3] + b201, 0.f);
            s10 += fmaxf(c[1][mt][0] + b210, 0.f) + fmaxf(c[1][mt][2] + b210, 0.f);
            s11 += fmaxf(c[1][mt][1] + b211, 0.f) + fmaxf(c[1][mt][3] + b211, 0.f);
        }
    }

    // reduce over the 8 lanes sharing t (lane bits 2,3,4)
    s00 += __shfl_xor_sync(0xffffffffu, s00, 4);
    s01 += __shfl_xor_sync(0xffffffffu, s01, 4);
    s10 += __shfl_xor_sync(0xffffffffu, s10, 4);
    s11 += __shfl_xor_sync(0xffffffffu, s11, 4);
    s00 += __shfl_xor_sync(0xffffffffu, s00, 8);
    s01 += __shfl_xor_sync(0xffffffffu, s01, 8);
    s10 += __shfl_xor_sync(0xffffffffu, s10, 8);
    s11 += __shfl_xor_sync(0xffffffffu, s11, 8);
    s00 += __shfl_xor_sync(0xffffffffu, s00, 16);
    s01 += __shfl_xor_sync(0xffffffffu, s01, 16);
    s10 += __shfl_xor_sync(0xffffffffu, s10, 16);
    s11 += __shfl_xor_sync(0xffffffffu, s11, 16);
    if (lane < 4) {
        s_col[colb0] = s00;
        s_col[colb0 + 1] = s01;
        s_col[colb1] = s10;
        s_col[colb1 + 1] = s11;
    }
    __syncthreads();
    if (tid < DD)
        atomicAdd(&out[(size_t)(row0 >> LOG2NPG) * DD + tid],
                  s_col[tid] * (1.0f / 512.0f));
}

// ---------------- launch ----------------
extern "C" void kernel_launch(void* const* d_in, const int* in_sizes, int n_in,
                              void* d_out, int out_size) {
    const int*   feat = (const int*)d_in[0];
    const int*   src  = (const int*)d_in[1];
    const int*   dst  = (const int*)d_in[2];
    const float* emb  = (const float*)d_in[3];
    const float* W1   = (const float*)d_in[4];
    const float* b1   = (const float*)d_in[5];
    const float* W2   = (const float*)d_in[6];
    const float* b2   = (const float*)d_in[7];
    float* out = (float*)d_out;

    int n = in_sizes[0];          // 131072
    int E = in_sizes[1];          // 2097152
    int nG = n >> LOG2NPG;        // 256 graphs
    int epg4 = (E / nG) >> 2;     // 2048 int4 per graph

    cudaFuncSetAttribute(k_agg, cudaFuncAttributeMaxDynamicSharedMemorySize, AGG_SMEM);
    cudaFuncSetAttribute(k_gemm, cudaFuncAttributeMaxDynamicSharedMemorySize, GEMM_SMEM);

    k_embinit<<< 128, 128 >>> (emb, W1, out, out_size);
    k_prep  <<< 24, 256 >>> (W2);
    k_agg   <<< nG, 1024, AGG_SMEM >>> (feat, b1, (const int4*)src, (const int4*)dst, epg4);
    k_gemm  <<< n / 128, 256, GEMM_SMEM >>> (b2, out);
}